// round 11
// baseline (speedup 1.0000x reference)
#include <cuda_runtime.h>
#include <cuda_bf16.h>
#include <cstdint>

// Problem dims
#define BSZ 16
#define NV  128
#define NT  64
#define DM  512
#define HEADS 8
#define HD  64
#define TOPKN 16
#define BATT (BSZ*NT)          // 1024
#define FULLMASK 0xffffffffu

#define HN ((size_t)BSZ*NV*NT*DM)   // 67,108,864 elements
#define QKN ((size_t)BATT*HEADS*NV*HD)

// ---------- scratch (device globals; no allocation allowed) ----------
__device__ __nv_bfloat16 g_Qhi[QKN];    // [B][H][V][hd], pre-scaled by 1/8
__device__ __nv_bfloat16 g_Qlo[QKN];
__device__ __nv_bfloat16 g_Khi[QKN];
__device__ __nv_bfloat16 g_Klo[QKN];
__device__ __nv_bfloat16 g_Vb[QKN];     // [B][H][V][hd] bf16
__device__ __nv_bfloat16 g_Hhi[HN];     // h split hi  [m][k], m=(b*128+v)*64+t
__device__ __nv_bfloat16 g_Hlo[HN];
__device__ __nv_bfloat16 g_Mhi[HN];     // mixed bf16 [m][k], m=(b*64+t)*128+v
__device__ __nv_bfloat16 g_Whi[4*DM*DM];  // Wq,Wk,Wv,Wo split hi [n][k]
__device__ __nv_bfloat16 g_Wlo[4*DM*DM];

// ---------- packed f32x2 helpers ----------
__device__ __forceinline__ unsigned long long pack2(float lo, float hi) {
    unsigned long long r;
    asm("mov.b64 %0, {%1, %2};" : "=l"(r) : "f"(lo), "f"(hi));
    return r;
}
__device__ __forceinline__ float2 unpack2(unsigned long long v) {
    float2 r;
    asm("mov.b64 {%0, %1}, %2;" : "=f"(r.x), "=f"(r.y) : "l"(v));
    return r;
}
__device__ __forceinline__ unsigned long long fma2(unsigned long long a,
                                                   unsigned long long b,
                                                   unsigned long long c) {
    unsigned long long d;
    asm("fma.rn.f32x2 %0, %1, %2, %3;" : "=l"(d) : "l"(a), "l"(b), "l"(c));
    return d;
}

// ---------- misc helpers ----------
__device__ __forceinline__ uint32_t smem_u32(const void* p) {
    uint32_t a;
    asm("{ .reg .u64 t; cvta.to.shared.u64 t, %1; cvt.u32.u64 %0, t; }"
        : "=r"(a) : "l"(p));
    return a;
}
__device__ __forceinline__ void split1(float x, __nv_bfloat16& h, __nv_bfloat16& l) {
    h = __float2bfloat16(x);
    l = __float2bfloat16(x - __bfloat162float(h));
}
__device__ __forceinline__ uint32_t redux_max_u32(uint32_t v) {
    uint32_t r;
    asm volatile("redux.sync.max.u32 %0, %1, 0xffffffff;" : "=r"(r) : "r"(v));
    return r;
}
// monotonic float->uint map (order-preserving)
__device__ __forceinline__ uint32_t f2u(float x) {
    uint32_t u = __float_as_uint(x);
    return u ^ (uint32_t)(((int32_t)u >> 31) | 0x80000000);
}
__device__ __forceinline__ float u2f(uint32_t u) {
    uint32_t x = (u >> 31) ? (u ^ 0x80000000u) : ~u;
    return __uint_as_float(x);
}
__device__ __forceinline__ void csw(uint32_t& a, uint32_t& b) {  // desc compare-swap
    uint32_t hi = max(a, b), lo = min(a, b);
    a = hi; b = lo;
}

// ---------- bf16 split pre-conversion kernels ----------
__global__ void __launch_bounds__(256) conv_h(const float* __restrict__ src) {
    size_t i = ((size_t)blockIdx.x * 256 + threadIdx.x) * 4;
    float4 f = *(const float4*)(src + i);
    __nv_bfloat16 h0,l0,h1,l1,h2,l2,h3,l3;
    split1(f.x,h0,l0); split1(f.y,h1,l1); split1(f.z,h2,l2); split1(f.w,h3,l3);
    ushort4 H = { __bfloat16_as_ushort(h0), __bfloat16_as_ushort(h1),
                  __bfloat16_as_ushort(h2), __bfloat16_as_ushort(h3) };
    ushort4 L = { __bfloat16_as_ushort(l0), __bfloat16_as_ushort(l1),
                  __bfloat16_as_ushort(l2), __bfloat16_as_ushort(l3) };
    *(ushort4*)(g_Hhi + i) = H;
    *(ushort4*)(g_Hlo + i) = L;
}

__global__ void __launch_bounds__(256) conv_w(const float* __restrict__ q,
                                              const float* __restrict__ k,
                                              const float* __restrict__ v,
                                              const float* __restrict__ o) {
    size_t i4 = (size_t)blockIdx.x * 256 + threadIdx.x;
    int w = (int)(i4 >> 16);
    const float* s = (w == 0) ? q : (w == 1) ? k : (w == 2) ? v : o;
    size_t loc = (i4 & 65535) * 4;
    size_t i = i4 * 4;
    float4 f = *(const float4*)(s + loc);
    __nv_bfloat16 h0,l0,h1,l1,h2,l2,h3,l3;
    split1(f.x,h0,l0); split1(f.y,h1,l1); split1(f.z,h2,l2); split1(f.w,h3,l3);
    ushort4 H = { __bfloat16_as_ushort(h0), __bfloat16_as_ushort(h1),
                  __bfloat16_as_ushort(h2), __bfloat16_as_ushort(h3) };
    ushort4 L = { __bfloat16_as_ushort(l0), __bfloat16_as_ushort(l1),
                  __bfloat16_as_ushort(l2), __bfloat16_as_ushort(l3) };
    *(ushort4*)(g_Whi + i) = H;
    *(ushort4*)(g_Wlo + i) = L;
}

// ---------- tensor-core GEMM: 256(M)x128(N) tile, 512 thr, 16 warps ----------
#define STAGE_B   49152         // Ahi 16K | Alo 16K | Bhi 8K | Blo 8K
#define GEMM_SMEM (3*STAGE_B)   // 3-stage ring, 144KB

__device__ __forceinline__ uint32_t swz(uint32_t off) {     // 64B rows
    return off ^ (((off >> 6) & 7) << 4);
}
__device__ __forceinline__ uint32_t swz128(uint32_t off) {  // 128B rows
    return off ^ (((off >> 7) & 7) << 4);
}

#define CPA16(dst, src) \
    asm volatile("cp.async.cg.shared.global [%0], [%1], 16;" :: "r"(dst), "l"(src))
#define CPCOMMIT() asm volatile("cp.async.commit_group;" ::: "memory")
#define CPWAIT(n)  asm volatile("cp.async.wait_group %0;" :: "n"(n) : "memory")

#define LDSM4(r, a) \
    asm volatile("ldmatrix.sync.aligned.m8n8.x4.shared.b16 {%0,%1,%2,%3}, [%4];" \
        : "=r"((r)[0]),"=r"((r)[1]),"=r"((r)[2]),"=r"((r)[3]) : "r"(a))

#define MMA16816(d, a, b0, b1) \
    asm volatile("mma.sync.aligned.m16n8k16.row.col.f32.bf16.bf16.f32 " \
        "{%0,%1,%2,%3},{%4,%5,%6,%7},{%8,%9},{%0,%1,%2,%3};" \
        : "+f"((d)[0]),"+f"((d)[1]),"+f"((d)[2]),"+f"((d)[3]) \
        : "r"((a)[0]),"r"((a)[1]),"r"((a)[2]),"r"((a)[3]), "r"(b0),"r"(b1))

// MODE 0: qkv (A=g_Hhi/lo, W = weight bx>>2). Q/K use 3 products; V uses 2.
// MODE 1: out-proj (A=g_Mhi only, W = Wo, 2 products, + residual)
template <int MODE>
__global__ void __launch_bounds__(512, 1) gemm_mma(
    const float* __restrict__ hres, float* __restrict__ outp)
{
    extern __shared__ char sm[];
    uint32_t sb = smem_u32(sm);
    int tid = threadIdx.x, lane = tid & 31, wid = tid >> 5;  // 16 warps
    int bx = blockIdx.x;
    int m0 = blockIdx.y * 256;
    int wsel, n0;
    if (MODE == 0) { wsel = bx >> 2; n0 = (bx & 3) * 128; }
    else           { wsel = 3;       n0 = bx * 128; }

    const bool useAlo = (MODE == 0) && (wsel != 2);   // CTA-uniform

    const __nv_bfloat16* Ahi = (MODE == 0) ? g_Hhi : g_Mhi;
    const __nv_bfloat16* Alo = (MODE == 0) ? g_Hlo : g_Mhi;  // MODE1: unused
    const __nv_bfloat16* Bhi = g_Whi + (size_t)wsel * DM * DM;
    const __nv_bfloat16* Blo = g_Wlo + (size_t)wsel * DM * DM;

    // stage slots: Ahi 0 | Alo 16384 | Bhi 32768 | Blo 40960
    auto loadc = [&](int c) {
        uint32_t stb = sb + (uint32_t)(c % 3) * STAGE_B;
        if (useAlo) {
#pragma unroll
            for (int i = 0; i < 6; i++) {
                int g = tid + i * 512;
                const __nv_bfloat16* src;
                uint32_t slotoff;
                int idx;
                if (i < 2)      { idx = g;        src = Ahi; slotoff = 0; }
                else if (i < 4) { idx = g - 1024; src = Alo; slotoff = 16384; }
                else if (i < 5) { idx = g - 2048; src = Bhi; slotoff = 32768; }
                else            { idx = g - 2560; src = Blo; slotoff = 40960; }
                int row = idx >> 2, kg = idx & 3;
                int rbase = (i < 4) ? m0 : n0;
                src += (size_t)(rbase + row) * 512 + c * 32 + kg * 8;
                uint32_t dst = stb + slotoff + swz((uint32_t)(row * 64 + kg * 16));
                CPA16(dst, src);
            }
        } else {
#pragma unroll
            for (int i = 0; i < 4; i++) {
                int g = tid + i * 512;
                const __nv_bfloat16* src;
                uint32_t slotoff;
                int idx;
                if (i < 2)      { idx = g;        src = Ahi; slotoff = 0; }
                else if (i < 3) { idx = g - 1024; src = Bhi; slotoff = 32768; }
                else            { idx = g - 1536; src = Blo; slotoff = 40960; }
                int row = idx >> 2, kg = idx & 3;
                int rbase = (i < 2) ? m0 : n0;
                src += (size_t)(rbase + row) * 512 + c * 32 + kg * 8;
                uint32_t dst = stb + slotoff + swz((uint32_t)(row * 64 + kg * 16));
                CPA16(dst, src);
            }
        }
        CPCOMMIT();
    };

    int wm = wid & 3, wn = wid >> 2;      // warp tile: 64(M) x 32(N)
    float acc[64];
#pragma unroll
    for (int i = 0; i < 64; i++) acc[i] = 0.f;

    loadc(0);
    loadc(1);
    for (int c = 0; c < 16; c++) {
        if (c == 15) { CPWAIT(0); } else { CPWAIT(1); }
        __syncthreads();                  // chunk c ready; slot (c+2)%3 free
        if (c + 2 < 16) loadc(c + 2);
        uint32_t stb = sb + (uint32_t)(c % 3) * STAGE_B;
#pragma unroll
        for (int ks = 0; ks < 2; ks++) {
            uint32_t ah[4][4];
            uint32_t al[4][4] = {{0,0,0,0},{0,0,0,0},{0,0,0,0},{0,0,0,0}};
#pragma unroll
            for (int mt = 0; mt < 4; mt++) {
                int r = wm * 64 + mt * 16 + (lane & 15);
                uint32_t off = swz((uint32_t)(r * 64 + (ks * 16 + (lane >> 4) * 8) * 2));
                LDSM4(ah[mt], stb + off);
                if (useAlo) LDSM4(al[mt], stb + 16384 + off);
            }
#pragma unroll
            for (int p = 0; p < 2; p++) {
                int rr = wn * 32 + (2 * p + (lane >> 4)) * 8 + (lane & 7);
                uint32_t off = swz((uint32_t)(rr * 64 + (ks * 16 + ((lane >> 3) & 1) * 8) * 2));
                uint32_t bh[4], bl[4];
                LDSM4(bh, stb + 32768 + off);
                LDSM4(bl, stb + 40960 + off);
#pragma unroll
                for (int pr = 0; pr < 3; pr++) {
                    if (pr == 2 && !useAlo) continue;   // V / out-proj: 2 products
#pragma unroll
                    for (int mt = 0; mt < 4; mt++) {
#pragma unroll
                        for (int q = 0; q < 2; q++) {
                            float* d = acc + mt * 16 + (2 * p + q) * 4;
                            const uint32_t* a = (pr == 2) ? al[mt] : ah[mt];
                            const uint32_t* b = (pr == 1) ? bl : bh;
                            MMA16816(d, a, b[2 * q], b[2 * q + 1]);
                        }
                    }
                }
            }
        }
    }

    // ---- epilogue ----
#pragma unroll
    for (int mt = 0; mt < 4; mt++) {
#pragma unroll
        for (int half = 0; half < 2; half++) {
            int m = m0 + wm * 64 + mt * 16 + half * 8 + (lane >> 2);
            if (MODE == 0) {
                int b = m >> 13, v = (m >> 6) & 127, t = m & 63;
#pragma unroll
                for (int nt = 0; nt < 4; nt++) {
                    int n = n0 + wn * 32 + nt * 8 + (lane & 3) * 2;
                    int head = n >> 6, hd = n & 63;
                    int base = mt * 16 + nt * 4 + half * 2;
                    float2 val = make_float2(acc[base], acc[base + 1]);
                    size_t g = (((size_t)(b * 64 + t) * 8 + head) * 128 + v) * 64 + hd;
                    if (wsel == 2) {
                        ushort2 V2 = { __bfloat16_as_ushort(__float2bfloat16(val.x)),
                                       __bfloat16_as_ushort(__float2bfloat16(val.y)) };
                        *(ushort2*)(g_Vb + g) = V2;
                    } else {
                        if (wsel == 0) { val.x *= 0.125f; val.y *= 0.125f; }
                        __nv_bfloat16 h0, l0, h1, l1;
                        split1(val.x, h0, l0);
                        split1(val.y, h1, l1);
                        ushort2 H = { __bfloat16_as_ushort(h0), __bfloat16_as_ushort(h1) };
                        ushort2 L = { __bfloat16_as_ushort(l0), __bfloat16_as_ushort(l1) };
                        if (wsel == 0) {
                            *(ushort2*)(g_Qhi + g) = H;
                            *(ushort2*)(g_Qlo + g) = L;
                        } else {
                            *(ushort2*)(g_Khi + g) = H;
                            *(ushort2*)(g_Klo + g) = L;
                        }
                    }
                }
            } else {
                int Bi = m >> 7, v = m & 127;
                int b = Bi >> 6, t = Bi & 63;
                size_t dbase = (((size_t)b * 128 + v) * 64 + t) * 512
                               + n0 + wn * 32 + (lane & 3) * 2;
#pragma unroll
                for (int nt = 0; nt < 4; nt++) {
                    int base = mt * 16 + nt * 4 + half * 2;
                    float2 val = make_float2(acc[base], acc[base + 1]);
                    size_t d = dbase + nt * 8;
                    float2 hv = *(const float2*)&hres[d];
                    val.x += hv.x; val.y += hv.y;
                    *(float2*)&outp[d] = val;
                }
            }
        }
    }
}

// =====================================================================
// Attention v6 (round-10 proven): 64 q-rows per CTA, bf16 V, 72KB smem,
// 3 CTA/SM. tensor-core scores + sorted-tournament top-16 + sparse AV.
// =====================================================================
#define AOFF_QHI 0                // [64][128B]  8KB
#define AOFF_QLO 8192             // 8KB
#define AOFF_KHI 16384            // [128][128B] 16KB
#define AOFF_KLO 32768            // 16KB  (Q/K end 49152)
#define AOFF_S   0                // overlays Q/KHI: fp32 [64][128] = 32KB
#define AOFF_V   49152            // bf16 [128][64] = 16KB
#define AOFF_PIDX 65536           // int  [64][16] = 4KB
#define AOFF_PVAL 69632           // f32  [64][16] = 4KB
#define ATT_SMEM 73728

// XOR bank-swizzled S index ([64][128] fp32)
__device__ __forceinline__ int sidx(int r, int c) {
    return r * 128 + (c ^ ((r & 7) << 2));
}

__device__ __forceinline__ void store_h(size_t idx, float2 v) {
    ushort2 H = { __bfloat16_as_ushort(__float2bfloat16(v.x)),
                  __bfloat16_as_ushort(__float2bfloat16(v.y)) };
    *(ushort2*)(g_Mhi + idx) = H;
}

__global__ void __launch_bounds__(256, 3) attn2() {
    extern __shared__ char sm[];
    uint32_t sb = smem_u32(sm);
    float* sS = (float*)(sm + AOFF_S);
    int*   sPidx = (int*)(sm + AOFF_PIDX);
    float* sPval = (float*)(sm + AOFF_PVAL);

    int tid = threadIdx.x, lane = tid & 31, wid = tid >> 5;
    int bx = blockIdx.x;                 // ((B*8+head)<<1) | half
    int bh = bx >> 1;
    int qr0 = (bx & 1) * 64;             // q-row offset within the 128
    size_t base = (size_t)bh * 8192;     // 128*64

    // zero compacted-P arrays
    for (int i = tid; i < 1024; i += 256) { sPidx[i] = 0; sPval[i] = 0.f; }

    // ---- async loads: Q half (64 rows), K full, V bf16 ----
#pragma unroll
    for (int i = 0; i < 2; i++) {
        int g = tid + i * 256;           // 0..511 (64 rows x 8 chunks)
        int row = g >> 3, kg = g & 7;
        uint32_t doff = swz128((uint32_t)(row * 128 + kg * 16));
        CPA16(sb + AOFF_QHI + doff, g_Qhi + base + (size_t)(qr0 + row) * 64 + kg * 8);
        CPA16(sb + AOFF_QLO + doff, g_Qlo + base + (size_t)(qr0 + row) * 64 + kg * 8);
    }
#pragma unroll
    for (int i = 0; i < 4; i++) {
        int g = tid + i * 256;           // 0..1023 (128 rows x 8 chunks)
        int row = g >> 3, kg = g & 7;
        uint32_t doff = swz128((uint32_t)(row * 128 + kg * 16));
        CPA16(sb + AOFF_KHI + doff, g_Khi + base + (size_t)row * 64 + kg * 8);
        CPA16(sb + AOFF_KLO + doff, g_Klo + base + (size_t)row * 64 + kg * 8);
    }
#pragma unroll
    for (int i = 0; i < 4; i++) {
        int g = tid + i * 256;           // 0..1023 chunks of 16B (16KB)
        CPA16(sb + AOFF_V + g * 16, g_Vb + base + g * 8);
    }
    CPCOMMIT();
    CPWAIT(0);
    __syncthreads();

    // ---- S = Q @ K^T via mma (3-product split). warp tile 32(M) x 32(N) ----
    {
        int wm = wid & 1, wn = wid >> 1;
        float acc[32];
#pragma unroll
        for (int i = 0; i < 32; i++) acc[i] = 0.f;
#pragma unroll
        for (int kt = 0; kt < 4; kt++) {
            uint32_t ah[2][4], al[2][4];
#pragma unroll
            for (int mt = 0; mt < 2; mt++) {
                int r = wm * 32 + mt * 16 + (lane & 15);
                uint32_t off = swz128((uint32_t)(r * 128 + (kt * 16 + (lane >> 4) * 8) * 2));
                LDSM4(ah[mt], sb + AOFF_QHI + off);
                LDSM4(al[mt], sb + AOFF_QLO + off);
            }
#pragma unroll
            for (int p = 0; p < 2; p++) {
                int rr = wn * 32 + (2 * p + (lane >> 4)) * 8 + (lane & 7);
                uint32_t off = swz128((uint32_t)(rr * 128 + (kt * 16 + ((lane >> 3) & 1) * 8) * 2));
                uint32_t bh4[4], bl4[4];
                LDSM4(bh4, sb + AOFF_KHI + off);
                LDSM4(bl4, sb + AOFF_KLO + off);
#pragma unroll
                for (int pr = 0; pr < 3; pr++) {
#pragma unroll
                    for (int mt = 0; mt < 2; mt++) {
#pragma unroll
                        for (int q = 0; q < 2; q++) {
                            float* d = acc + mt * 16 + (2 * p + q) * 4;
                            const uint32_t* a = (pr == 2) ? al[mt] : ah[mt];
                            const uint32_t* b = (pr == 1) ? bl4 : bh4;
                            MMA16816(d, a, b[2 * q], b[2 * q + 1]);
                        }
                    }
                }
            }
        }
        __syncthreads();   // all warps done reading Q/K before S overwrites them
        // store S to overlaid SMEM [64][128] with XOR swizzle
#pragma unroll
        for (int mt = 0; mt < 2; mt++) {
#pragma unroll
            for (int half = 0; half < 2; half++) {
                int r = wm * 32 + mt * 16 + half * 8 + (lane >> 2);
#pragma unroll
                for (int nt = 0; nt < 4; nt++) {
                    int col = wn * 32 + nt * 8 + (lane & 3) * 2;
                    int bi = mt * 16 + nt * 4 + half * 2;
                    *(float2*)&sS[sidx(r, col)] = make_float2(acc[bi], acc[bi + 1]);
                }
            }
        }
    }
    __syncthreads();

    // ---- top-16 (sorted tournament) + softmax, warp per 2 rows ----
    for (int i = 0; i < 4; i++) {
        int r0 = wid * 8 + 2 * i;
        int r1 = r0 + 1;
        float4 f0 = *(float4*)&sS[sidx(r0, lane * 4)];
        float4 f1 = *(float4*)&sS[sidx(r1, lane * 4)];
        float fa0[4] = { f0.x, f0.y, f0.z, f0.w };
        float fa1[4] = { f1.x, f1.y, f1.z, f1.w };
        uint32_t uo0[4], uo1[4], u0[4], u1[4];
#pragma unroll
        for (int e = 0; e < 4; e++) {
            uo0[e] = u0[e] = f2u(fa0[e]);
            uo1[e] = u1[e] = f2u(fa1[e]);
        }
        // per-lane descending sort of 4 values (sorting network)
        csw(u0[0], u0[2]); csw(u0[1], u0[3]);
        csw(u0[0], u0[1]); csw(u0[2], u0[3]); csw(u0[1], u0[2]);
        csw(u1[0], u1[2]); csw(u1[1], u1[3]);
        csw(u1[0], u1[1]); csw(u1[2], u1[3]); csw(u1[1], u1[2]);

        float rm0 = 0.f, rm1 = 0.f;
        uint32_t th0 = 0, th1 = 0;
#pragma unroll 1
        for (int it = 0; it < TOPKN; it++) {
            uint32_t g0 = redux_max_u32(u0[0]);
            uint32_t g1 = redux_max_u32(u1[0]);
            if (it == 0) { rm0 = u2f(g0); rm1 = u2f(g1); }
            th0 = g0; th1 = g1;
            bool t0 = (u0[0] == g0);
            bool t1 = (u1[0] == g1);
            u0[0] = t0 ? u0[1] : u0[0];
            u0[1] = t0 ? u0[2] : u0[1];
            u0[2] = t0 ? u0[3] : u0[2];
            u0[3] = t0 ? 0u    : u0[3];
            u1[0] = t1 ? u1[1] : u1[0];
            u1[1] = t1 ? u1[2] : u1[1];
            u1[2] = t1 ? u1[3] : u1[2];
            u1[3] = t1 ? 0u    : u1[3];
        }
        float p0[4], p1[4];
        float s0 = 0.f, s1 = 0.f;
#pragma unroll
        for (int e = 0; e < 4; e++) {
            p0[e] = (uo0[e] >= th0) ? __expf(fa0[e] - rm0) : 0.f;
            p1[e] = (uo1[e] >= th1) ? __expf(fa1[e] - rm1) : 0.f;
            s0 += p0[e]; s1 += p1[e];
        }
#pragma unroll
        for (int o = 16; o; o >>= 1) {
            s0 += __shfl_xor_sync(FULLMASK, s0, o);
            s1 += __shfl_xor_sync(FULLMASK, s1, o);
        }
        float inv0 = 1.0f / s0, inv1 = 1.0f / s1;
        // compact (idx, p) into 16-entry lists
        int bc0 = 0, bc1 = 0;
#pragma unroll
        for (int e = 0; e < 4; e++) {
            uint32_t b0 = __ballot_sync(FULLMASK, p0[e] > 0.f);
            uint32_t b1 = __ballot_sync(FULLMASK, p1[e] > 0.f);
            uint32_t lt = (1u << lane) - 1u;
            if (p0[e] > 0.f) {
                int pos = bc0 + __popc(b0 & lt);
                if (pos < 16) { sPidx[r0 * 16 + pos] = lane * 4 + e;
                                sPval[r0 * 16 + pos] = p0[e] * inv0; }
            }
            if (p1[e] > 0.f) {
                int pos = bc1 + __popc(b1 & lt);
                if (pos < 16) { sPidx[r1 * 16 + pos] = lane * 4 + e;
                                sPval[r1 * 16 + pos] = p1[e] * inv1; }
            }
            bc0 += __popc(b0);
            bc1 += __popc(b1);
        }
    }
    __syncthreads();

    // ---- sparse AV over bf16 V: mixed[r] = sum_j p_j * V[idx_j] ----
    int B = bh >> 3, hh = bh & 7;
    const uint32_t* sVb = (const uint32_t*)(sm + AOFF_V);   // bf16x2 units
    for (int i = 0; i < 4; i++) {
        int r0 = wid * 8 + 2 * i;
        int r1 = r0 + 1;
        unsigned long long a0 = 0, a1 = 0;
#pragma unroll
        for (int j = 0; j < 16; j++) {
            int i0 = sPidx[r0 * 16 + j];
            int i1 = sPidx[r1 * 16 + j];
            float q0 = sPval[r0 * 16 + j];
            float q1 = sPval[r1 * 16 + j];
            uint32_t v0 = sVb[i0 * 32 + lane];   // bf16x2 (cols lane*2, +1)
            uint32_t v1 = sVb[i1 * 32 + lane];
            unsigned long long vv0 = pack2(__uint_as_float(v0 << 16),
                                           __uint_as_float(v0 & 0xffff0000u));
            unsigned long long vv1 = pack2(__uint_as_float(v1 << 16),
                                           __uint_as_float(v1 & 0xffff0000u));
            a0 = fma2(pack2(q0, q0), vv0, a0);
            a1 = fma2(pack2(q1, q1), vv1, a1);
        }
        size_t o0 = ((size_t)B * 128 + qr0 + r0) * 512 + hh * 64 + lane * 2;
        store_h(o0, unpack2(a0));
        store_h(o0 + 512, unpack2(a1));
    }
}

// =====================================================================
extern "C" void kernel_launch(void* const* d_in, const int* in_sizes, int n_in,
                              void* d_out, int out_size) {
    const float* h  = (const float*)d_in[0];
    const float* Wq = (const float*)d_in[1];
    const float* Wk = (const float*)d_in[2];
    const float* Wv = (const float*)d_in[3];
    const float* Wo = (const float*)d_in[4];
    float* out = (float*)d_out;

    cudaFuncSetAttribute(gemm_mma<0>, cudaFuncAttributeMaxDynamicSharedMemorySize, GEMM_SMEM);
    cudaFuncSetAttribute(gemm_mma<1>, cudaFuncAttributeMaxDynamicSharedMemorySize, GEMM_SMEM);
    cudaFuncSetAttribute(attn2, cudaFuncAttributeMaxDynamicSharedMemorySize, ATT_SMEM);

    conv_h<<<65536, 256>>>(h);
    conv_w<<<1024, 256>>>(Wq, Wk, Wv, Wo);
    gemm_mma<0><<<dim3(12, 512), 512, GEMM_SMEM>>>(nullptr, nullptr);
    attn2<<<16384, 256, ATT_SMEM>>>();
    gemm_mma<1><<<dim3(4, 512), 512, GEMM_SMEM>>>(h, out);
}

// round 12
// speedup vs baseline: 1.0469x; 1.0469x over previous
#include <cuda_runtime.h>
#include <cuda_bf16.h>
#include <cstdint>

// Problem dims
#define BSZ 16
#define NV  128
#define NT  64
#define DM  512
#define HEADS 8
#define HD  64
#define TOPKN 16
#define BATT (BSZ*NT)          // 1024
#define FULLMASK 0xffffffffu

#define HN ((size_t)BSZ*NV*NT*DM)   // 67,108,864 elements
#define QKN ((size_t)BATT*HEADS*NV*HD)

// ---------- scratch (device globals; no allocation allowed) ----------
__device__ __nv_bfloat16 g_Qhi[QKN];    // [B][H][V][hd], pre-scaled by 1/8
__device__ __nv_bfloat16 g_Qlo[QKN];
__device__ __nv_bfloat16 g_Khi[QKN];
__device__ __nv_bfloat16 g_Klo[QKN];
__device__ __nv_bfloat16 g_Vb[QKN];     // [B][H][V][hd] bf16
__device__ __nv_bfloat16 g_Hhi[HN];     // h split hi  [m][k], m=(b*128+v)*64+t
__device__ __nv_bfloat16 g_Hlo[HN];
__device__ __nv_bfloat16 g_Mhi[HN];     // mixed bf16 [m][k], m=(b*64+t)*128+v
__device__ __nv_bfloat16 g_Whi[4*DM*DM];  // Wq,Wk,Wv,Wo split hi [n][k]
__device__ __nv_bfloat16 g_Wlo[4*DM*DM];

// ---------- packed f32x2 helpers ----------
__device__ __forceinline__ unsigned long long pack2(float lo, float hi) {
    unsigned long long r;
    asm("mov.b64 %0, {%1, %2};" : "=l"(r) : "f"(lo), "f"(hi));
    return r;
}
__device__ __forceinline__ float2 unpack2(unsigned long long v) {
    float2 r;
    asm("mov.b64 {%0, %1}, %2;" : "=f"(r.x), "=f"(r.y) : "l"(v));
    return r;
}
__device__ __forceinline__ unsigned long long fma2(unsigned long long a,
                                                   unsigned long long b,
                                                   unsigned long long c) {
    unsigned long long d;
    asm("fma.rn.f32x2 %0, %1, %2, %3;" : "=l"(d) : "l"(a), "l"(b), "l"(c));
    return d;
}

// ---------- misc helpers ----------
__device__ __forceinline__ uint32_t smem_u32(const void* p) {
    uint32_t a;
    asm("{ .reg .u64 t; cvta.to.shared.u64 t, %1; cvt.u32.u64 %0, t; }"
        : "=r"(a) : "l"(p));
    return a;
}
__device__ __forceinline__ void split1(float x, __nv_bfloat16& h, __nv_bfloat16& l) {
    h = __float2bfloat16(x);
    l = __float2bfloat16(x - __bfloat162float(h));
}
__device__ __forceinline__ uint32_t redux_max_u32(uint32_t v) {
    uint32_t r;
    asm volatile("redux.sync.max.u32 %0, %1, 0xffffffff;" : "=r"(r) : "r"(v));
    return r;
}
// monotonic float->uint map (order-preserving)
__device__ __forceinline__ uint32_t f2u(float x) {
    uint32_t u = __float_as_uint(x);
    return u ^ (uint32_t)(((int32_t)u >> 31) | 0x80000000);
}
__device__ __forceinline__ float u2f(uint32_t u) {
    uint32_t x = (u >> 31) ? (u ^ 0x80000000u) : ~u;
    return __uint_as_float(x);
}
__device__ __forceinline__ void csw(uint32_t& a, uint32_t& b) {  // desc compare-swap
    uint32_t hi = max(a, b), lo = min(a, b);
    a = hi; b = lo;
}

// ---------- bf16 split pre-conversion kernels ----------
__global__ void __launch_bounds__(256) conv_h(const float* __restrict__ src) {
    size_t i = ((size_t)blockIdx.x * 256 + threadIdx.x) * 4;
    float4 f = *(const float4*)(src + i);
    __nv_bfloat16 h0,l0,h1,l1,h2,l2,h3,l3;
    split1(f.x,h0,l0); split1(f.y,h1,l1); split1(f.z,h2,l2); split1(f.w,h3,l3);
    ushort4 H = { __bfloat16_as_ushort(h0), __bfloat16_as_ushort(h1),
                  __bfloat16_as_ushort(h2), __bfloat16_as_ushort(h3) };
    ushort4 L = { __bfloat16_as_ushort(l0), __bfloat16_as_ushort(l1),
                  __bfloat16_as_ushort(l2), __bfloat16_as_ushort(l3) };
    *(ushort4*)(g_Hhi + i) = H;
    *(ushort4*)(g_Hlo + i) = L;
}

__global__ void __launch_bounds__(256) conv_w(const float* __restrict__ q,
                                              const float* __restrict__ k,
                                              const float* __restrict__ v,
                                              const float* __restrict__ o) {
    size_t i4 = (size_t)blockIdx.x * 256 + threadIdx.x;
    int w = (int)(i4 >> 16);
    const float* s = (w == 0) ? q : (w == 1) ? k : (w == 2) ? v : o;
    size_t loc = (i4 & 65535) * 4;
    size_t i = i4 * 4;
    float4 f = *(const float4*)(s + loc);
    __nv_bfloat16 h0,l0,h1,l1,h2,l2,h3,l3;
    split1(f.x,h0,l0); split1(f.y,h1,l1); split1(f.z,h2,l2); split1(f.w,h3,l3);
    ushort4 H = { __bfloat16_as_ushort(h0), __bfloat16_as_ushort(h1),
                  __bfloat16_as_ushort(h2), __bfloat16_as_ushort(h3) };
    ushort4 L = { __bfloat16_as_ushort(l0), __bfloat16_as_ushort(l1),
                  __bfloat16_as_ushort(l2), __bfloat16_as_ushort(l3) };
    *(ushort4*)(g_Whi + i) = H;
    *(ushort4*)(g_Wlo + i) = L;
}

// ---------- tensor-core GEMM (round-10 proven: 128x128, 256thr, 2 CTA/SM) ----------
#define STAGE_B   32768
#define GEMM_SMEM (3*STAGE_B)   // 3-stage ring, 96KB

__device__ __forceinline__ uint32_t swz(uint32_t off) {     // 64B rows
    return off ^ (((off >> 6) & 7) << 4);
}
__device__ __forceinline__ uint32_t swz128(uint32_t off) {  // 128B rows
    return off ^ (((off >> 7) & 7) << 4);
}

#define CPA16(dst, src) \
    asm volatile("cp.async.cg.shared.global [%0], [%1], 16;" :: "r"(dst), "l"(src))
#define CPCOMMIT() asm volatile("cp.async.commit_group;" ::: "memory")
#define CPWAIT(n)  asm volatile("cp.async.wait_group %0;" :: "n"(n) : "memory")

#define LDSM4(r, a) \
    asm volatile("ldmatrix.sync.aligned.m8n8.x4.shared.b16 {%0,%1,%2,%3}, [%4];" \
        : "=r"((r)[0]),"=r"((r)[1]),"=r"((r)[2]),"=r"((r)[3]) : "r"(a))

#define MMA16816(d, a, b0, b1) \
    asm volatile("mma.sync.aligned.m16n8k16.row.col.f32.bf16.bf16.f32 " \
        "{%0,%1,%2,%3},{%4,%5,%6,%7},{%8,%9},{%0,%1,%2,%3};" \
        : "+f"((d)[0]),"+f"((d)[1]),"+f"((d)[2]),"+f"((d)[3]) \
        : "r"((a)[0]),"r"((a)[1]),"r"((a)[2]),"r"((a)[3]), "r"(b0),"r"(b1))

// MODE 0: qkv (A=g_Hhi/lo, W = weight bx>>2). Q/K use 3 products; V uses 2.
// MODE 1: out-proj (A=g_Mhi only, W = Wo, 2 products, + residual)
template <int MODE>
__global__ void __launch_bounds__(256, 2) gemm_mma(
    const float* __restrict__ hres, float* __restrict__ outp)
{
    extern __shared__ char sm[];
    uint32_t sb = smem_u32(sm);
    int tid = threadIdx.x, lane = tid & 31, wid = tid >> 5;
    int bx = blockIdx.x;
    int m0 = blockIdx.y * 128;
    int wsel, n0;
    if (MODE == 0) { wsel = bx >> 2; n0 = (bx & 3) * 128; }
    else           { wsel = 3;       n0 = bx * 128; }

    const bool useAlo = (MODE == 0) && (wsel != 2);   // CTA-uniform

    const __nv_bfloat16* Ahi = (MODE == 0) ? g_Hhi : g_Mhi;
    const __nv_bfloat16* Alo = (MODE == 0) ? g_Hlo : g_Mhi;  // MODE1: unused
    const __nv_bfloat16* Bhi = g_Whi + (size_t)wsel * DM * DM;
    const __nv_bfloat16* Blo = g_Wlo + (size_t)wsel * DM * DM;

    // 4-tile load (Ahi, Alo, Bhi, Blo) or 3-tile (skip Alo) when unused
    auto loadc = [&](int c) {
        uint32_t stb = sb + (uint32_t)(c % 3) * STAGE_B;
        if (useAlo) {
#pragma unroll
            for (int i = 0; i < 8; i++) {
                int g = tid + i * 256;
                int tile = g >> 9;
                int idx = g & 511;
                int row = idx >> 2, kg = idx & 3;
                const __nv_bfloat16* src;
                if (tile == 0)      src = Ahi + (size_t)(m0 + row) * 512;
                else if (tile == 1) src = Alo + (size_t)(m0 + row) * 512;
                else if (tile == 2) src = Bhi + (size_t)(n0 + row) * 512;
                else                src = Blo + (size_t)(n0 + row) * 512;
                src += c * 32 + kg * 8;
                uint32_t dst = stb + tile * 8192 + swz((uint32_t)(row * 64 + kg * 16));
                CPA16(dst, src);
            }
        } else {
#pragma unroll
            for (int i = 0; i < 6; i++) {
                int g = tid + i * 256;              // 0..1535
                int tile = g >> 9;                  // 0:Ahi 1:Bhi 2:Blo
                int idx = g & 511;
                int row = idx >> 2, kg = idx & 3;
                const __nv_bfloat16* src;
                int slot;
                if (tile == 0)      { src = Ahi + (size_t)(m0 + row) * 512; slot = 0; }
                else if (tile == 1) { src = Bhi + (size_t)(n0 + row) * 512; slot = 2; }
                else                { src = Blo + (size_t)(n0 + row) * 512; slot = 3; }
                src += c * 32 + kg * 8;
                uint32_t dst = stb + slot * 8192 + swz((uint32_t)(row * 64 + kg * 16));
                CPA16(dst, src);
            }
        }
        CPCOMMIT();
    };

    int wm = wid & 3, wn = wid >> 2;      // warp tile: 32(M) x 64(N)
    float acc[64];
#pragma unroll
    for (int i = 0; i < 64; i++) acc[i] = 0.f;

    loadc(0);
    loadc(1);
    for (int c = 0; c < 16; c++) {
        if (c == 15) { CPWAIT(0); } else { CPWAIT(1); }
        __syncthreads();                  // chunk c ready; slot (c+2)%3 free
        if (c + 2 < 16) loadc(c + 2);
        uint32_t stb = sb + (uint32_t)(c % 3) * STAGE_B;
#pragma unroll
        for (int ks = 0; ks < 2; ks++) {
            uint32_t ah[2][4];
            uint32_t al[2][4] = {{0,0,0,0},{0,0,0,0}};
#pragma unroll
            for (int mt = 0; mt < 2; mt++) {
                int r = wm * 32 + mt * 16 + (lane & 15);
                uint32_t off = swz((uint32_t)(r * 64 + (ks * 16 + (lane >> 4) * 8) * 2));
                LDSM4(ah[mt], stb + off);
                if (useAlo) LDSM4(al[mt], stb + 8192 + off);
            }
#pragma unroll
            for (int p = 0; p < 4; p++) {
                int rr = wn * 64 + (2 * p + (lane >> 4)) * 8 + (lane & 7);
                uint32_t off = swz((uint32_t)(rr * 64 + (ks * 16 + ((lane >> 3) & 1) * 8) * 2));
                uint32_t bh[4], bl[4];
                LDSM4(bh, stb + 16384 + off);
                LDSM4(bl, stb + 24576 + off);
#pragma unroll
                for (int pr = 0; pr < 3; pr++) {
                    if (pr == 2 && !useAlo) continue;   // V / out-proj: 2 products
#pragma unroll
                    for (int mt = 0; mt < 2; mt++) {
#pragma unroll
                        for (int q = 0; q < 2; q++) {
                            float* d = acc + mt * 32 + (2 * p + q) * 4;
                            const uint32_t* a = (pr == 2) ? al[mt] : ah[mt];
                            const uint32_t* b = (pr == 1) ? bl : bh;
                            MMA16816(d, a, b[2 * q], b[2 * q + 1]);
                        }
                    }
                }
            }
        }
    }

    // ---- epilogue ----
#pragma unroll
    for (int mt = 0; mt < 2; mt++) {
#pragma unroll
        for (int half = 0; half < 2; half++) {
            int m = m0 + wm * 32 + mt * 16 + half * 8 + (lane >> 2);
            if (MODE == 0) {
                int b = m >> 13, v = (m >> 6) & 127, t = m & 63;
                int head = (n0 >> 6) + wn;
                size_t rb = (((size_t)(b * 64 + t) * 8 + head) * 128 + v) * 64
                            + (lane & 3) * 2;
#pragma unroll
                for (int nt = 0; nt < 8; nt++) {
                    int base = mt * 32 + nt * 4 + half * 2;
                    float2 val = make_float2(acc[base], acc[base + 1]);
                    size_t g = rb + nt * 8;
                    if (wsel == 2) {
                        ushort2 V2 = { __bfloat16_as_ushort(__float2bfloat16(val.x)),
                                       __bfloat16_as_ushort(__float2bfloat16(val.y)) };
                        *(ushort2*)(g_Vb + g) = V2;
                    } else {
                        if (wsel == 0) { val.x *= 0.125f; val.y *= 0.125f; }
                        __nv_bfloat16 h0, l0, h1, l1;
                        split1(val.x, h0, l0);
                        split1(val.y, h1, l1);
                        ushort2 H = { __bfloat16_as_ushort(h0), __bfloat16_as_ushort(h1) };
                        ushort2 L = { __bfloat16_as_ushort(l0), __bfloat16_as_ushort(l1) };
                        if (wsel == 0) {
                            *(ushort2*)(g_Qhi + g) = H;
                            *(ushort2*)(g_Qlo + g) = L;
                        } else {
                            *(ushort2*)(g_Khi + g) = H;
                            *(ushort2*)(g_Klo + g) = L;
                        }
                    }
                }
            } else {
                int Bi = m >> 7, v = m & 127;
                int b = Bi >> 6, t = Bi & 63;
                size_t dbase = (((size_t)b * 128 + v) * 64 + t) * 512
                               + n0 + wn * 64 + (lane & 3) * 2;
#pragma unroll
                for (int nt = 0; nt < 8; nt++) {
                    int base = mt * 32 + nt * 4 + half * 2;
                    float2 val = make_float2(acc[base], acc[base + 1]);
                    size_t d = dbase + nt * 8;
                    float2 hv = *(const float2*)&hres[d];
                    val.x += hv.x; val.y += hv.y;
                    *(float2*)&outp[d] = val;
                }
            }
        }
    }
}

// =====================================================================
// Attention v7: round-10 structure + packed (idx,p) float2 lists.
// 64 q-rows per CTA (grid 16384), bf16 V, 72KB smem, 3 CTA/SM.
// =====================================================================
#define AOFF_QHI 0                // [64][128B]  8KB
#define AOFF_QLO 8192             // 8KB
#define AOFF_KHI 16384            // [128][128B] 16KB
#define AOFF_KLO 32768            // 16KB  (Q/K end 49152)
#define AOFF_S   0                // overlays Q/KHI: fp32 [64][128] = 32KB
#define AOFF_V   49152            // bf16 [128][64] = 16KB
#define AOFF_P   65536            // float2 [64][16] = 8KB  (idx bits, p)
#define ATT_SMEM 73728

// XOR bank-swizzled S index ([64][128] fp32)
__device__ __forceinline__ int sidx(int r, int c) {
    return r * 128 + (c ^ ((r & 7) << 2));
}

__device__ __forceinline__ void store_h(size_t idx, float2 v) {
    ushort2 H = { __bfloat16_as_ushort(__float2bfloat16(v.x)),
                  __bfloat16_as_ushort(__float2bfloat16(v.y)) };
    *(ushort2*)(g_Mhi + idx) = H;
}

__global__ void __launch_bounds__(256, 3) attn2() {
    extern __shared__ char sm[];
    uint32_t sb = smem_u32(sm);
    float* sS = (float*)(sm + AOFF_S);
    float2* sP = (float2*)(sm + AOFF_P);

    int tid = threadIdx.x, lane = tid & 31, wid = tid >> 5;
    int bx = blockIdx.x;                 // ((B*8+head)<<1) | half
    int bh = bx >> 1;
    int qr0 = (bx & 1) * 64;             // q-row offset within the 128
    size_t base = (size_t)bh * 8192;     // 128*64

    // zero compacted-P arrays (idx bits 0 = row 0, p 0 -> harmless)
    for (int i = tid; i < 1024; i += 256) sP[i] = make_float2(0.f, 0.f);

    // ---- async loads: Q half (64 rows), K full, V bf16 ----
#pragma unroll
    for (int i = 0; i < 2; i++) {
        int g = tid + i * 256;           // 0..511 (64 rows x 8 chunks)
        int row = g >> 3, kg = g & 7;
        uint32_t doff = swz128((uint32_t)(row * 128 + kg * 16));
        CPA16(sb + AOFF_QHI + doff, g_Qhi + base + (size_t)(qr0 + row) * 64 + kg * 8);
        CPA16(sb + AOFF_QLO + doff, g_Qlo + base + (size_t)(qr0 + row) * 64 + kg * 8);
    }
#pragma unroll
    for (int i = 0; i < 4; i++) {
        int g = tid + i * 256;           // 0..1023 (128 rows x 8 chunks)
        int row = g >> 3, kg = g & 7;
        uint32_t doff = swz128((uint32_t)(row * 128 + kg * 16));
        CPA16(sb + AOFF_KHI + doff, g_Khi + base + (size_t)row * 64 + kg * 8);
        CPA16(sb + AOFF_KLO + doff, g_Klo + base + (size_t)row * 64 + kg * 8);
    }
#pragma unroll
    for (int i = 0; i < 4; i++) {
        int g = tid + i * 256;           // 0..1023 chunks of 16B (16KB)
        CPA16(sb + AOFF_V + g * 16, g_Vb + base + g * 8);
    }
    CPCOMMIT();
    CPWAIT(0);
    __syncthreads();

    // ---- S = Q @ K^T via mma (3-product split). warp tile 32(M) x 32(N) ----
    {
        int wm = wid & 1, wn = wid >> 1;
        float acc[32];
#pragma unroll
        for (int i = 0; i < 32; i++) acc[i] = 0.f;
#pragma unroll
        for (int kt = 0; kt < 4; kt++) {
            uint32_t ah[2][4], al[2][4];
#pragma unroll
            for (int mt = 0; mt < 2; mt++) {
                int r = wm * 32 + mt * 16 + (lane & 15);
                uint32_t off = swz128((uint32_t)(r * 128 + (kt * 16 + (lane >> 4) * 8) * 2));
                LDSM4(ah[mt], sb + AOFF_QHI + off);
                LDSM4(al[mt], sb + AOFF_QLO + off);
            }
#pragma unroll
            for (int p = 0; p < 2; p++) {
                int rr = wn * 32 + (2 * p + (lane >> 4)) * 8 + (lane & 7);
                uint32_t off = swz128((uint32_t)(rr * 128 + (kt * 16 + ((lane >> 3) & 1) * 8) * 2));
                uint32_t bh4[4], bl4[4];
                LDSM4(bh4, sb + AOFF_KHI + off);
                LDSM4(bl4, sb + AOFF_KLO + off);
#pragma unroll
                for (int pr = 0; pr < 3; pr++) {
#pragma unroll
                    for (int mt = 0; mt < 2; mt++) {
#pragma unroll
                        for (int q = 0; q < 2; q++) {
                            float* d = acc + mt * 16 + (2 * p + q) * 4;
                            const uint32_t* a = (pr == 2) ? al[mt] : ah[mt];
                            const uint32_t* b = (pr == 1) ? bl4 : bh4;
                            MMA16816(d, a, b[2 * q], b[2 * q + 1]);
                        }
                    }
                }
            }
        }
        __syncthreads();   // all warps done reading Q/K before S overwrites them
        // store S to overlaid SMEM [64][128] with XOR swizzle
#pragma unroll
        for (int mt = 0; mt < 2; mt++) {
#pragma unroll
            for (int half = 0; half < 2; half++) {
                int r = wm * 32 + mt * 16 + half * 8 + (lane >> 2);
#pragma unroll
                for (int nt = 0; nt < 4; nt++) {
                    int col = wn * 32 + nt * 8 + (lane & 3) * 2;
                    int bi = mt * 16 + nt * 4 + half * 2;
                    *(float2*)&sS[sidx(r, col)] = make_float2(acc[bi], acc[bi + 1]);
                }
            }
        }
    }
    __syncthreads();

    // ---- top-16 (sorted tournament) + softmax, warp per 2 rows ----
    for (int i = 0; i < 4; i++) {
        int r0 = wid * 8 + 2 * i;
        int r1 = r0 + 1;
        float4 f0 = *(float4*)&sS[sidx(r0, lane * 4)];
        float4 f1 = *(float4*)&sS[sidx(r1, lane * 4)];
        float fa0[4] = { f0.x, f0.y, f0.z, f0.w };
        float fa1[4] = { f1.x, f1.y, f1.z, f1.w };
        uint32_t uo0[4], uo1[4], u0[4], u1[4];
#pragma unroll
        for (int e = 0; e < 4; e++) {
            uo0[e] = u0[e] = f2u(fa0[e]);
            uo1[e] = u1[e] = f2u(fa1[e]);
        }
        // per-lane descending sort of 4 values (sorting network)
        csw(u0[0], u0[2]); csw(u0[1], u0[3]);
        csw(u0[0], u0[1]); csw(u0[2], u0[3]); csw(u0[1], u0[2]);
        csw(u1[0], u1[2]); csw(u1[1], u1[3]);
        csw(u1[0], u1[1]); csw(u1[2], u1[3]); csw(u1[1], u1[2]);

        float rm0 = 0.f, rm1 = 0.f;
        uint32_t th0 = 0, th1 = 0;
#pragma unroll 1
        for (int it = 0; it < TOPKN; it++) {
            uint32_t g0 = redux_max_u32(u0[0]);
            uint32_t g1 = redux_max_u32(u1[0]);
            if (it == 0) { rm0 = u2f(g0); rm1 = u2f(g1); }
            th0 = g0; th1 = g1;
            bool t0 = (u0[0] == g0);
            bool t1 = (u1[0] == g1);
            u0[0] = t0 ? u0[1] : u0[0];
            u0[1] = t0 ? u0[2] : u0[1];
            u0[2] = t0 ? u0[3] : u0[2];
            u0[3] = t0 ? 0u    : u0[3];
            u1[0] = t1 ? u1[1] : u1[0];
            u1[1] = t1 ? u1[2] : u1[1];
            u1[2] = t1 ? u1[3] : u1[2];
            u1[3] = t1 ? 0u    : u1[3];
        }
        float p0[4], p1[4];
        float s0 = 0.f, s1 = 0.f;
#pragma unroll
        for (int e = 0; e < 4; e++) {
            p0[e] = (uo0[e] >= th0) ? __expf(fa0[e] - rm0) : 0.f;
            p1[e] = (uo1[e] >= th1) ? __expf(fa1[e] - rm1) : 0.f;
            s0 += p0[e]; s1 += p1[e];
        }
#pragma unroll
        for (int o = 16; o; o >>= 1) {
            s0 += __shfl_xor_sync(FULLMASK, s0, o);
            s1 += __shfl_xor_sync(FULLMASK, s1, o);
        }
        float inv0 = 1.0f / s0, inv1 = 1.0f / s1;
        // compact packed (idx, p) into 16-entry float2 lists
        int bc0 = 0, bc1 = 0;
#pragma unroll
        for (int e = 0; e < 4; e++) {
            uint32_t b0 = __ballot_sync(FULLMASK, p0[e] > 0.f);
            uint32_t b1 = __ballot_sync(FULLMASK, p1[e] > 0.f);
            uint32_t lt = (1u << lane) - 1u;
            if (p0[e] > 0.f) {
                int pos = bc0 + __popc(b0 & lt);
                if (pos < 16)
                    sP[r0 * 16 + pos] =
                        make_float2(__int_as_float(lane * 4 + e), p0[e] * inv0);
            }
            if (p1[e] > 0.f) {
                int pos = bc1 + __popc(b1 & lt);
                if (pos < 16)
                    sP[r1 * 16 + pos] =
                        make_float2(__int_as_float(lane * 4 + e), p1[e] * inv1);
            }
            bc0 += __popc(b0);
            bc1 += __popc(b1);
        }
    }
    __syncthreads();

    // ---- sparse AV over bf16 V: mixed[r] = sum_j p_j * V[idx_j] ----
    int B = bh >> 3, hh = bh & 7;
    const uint32_t* sVb = (const uint32_t*)(sm + AOFF_V);   // bf16x2 units
    for (int i = 0; i < 4; i++) {
        int r0 = wid * 8 + 2 * i;
        int r1 = r0 + 1;
        unsigned long long a0 = 0, a1 = 0;
#pragma unroll
        for (int j = 0; j < 16; j++) {
            float2 e0 = sP[r0 * 16 + j];
            float2 e1 = sP[r1 * 16 + j];
            int i0 = __float_as_int(e0.x);
            int i1 = __float_as_int(e1.x);
            uint32_t v0 = sVb[i0 * 32 + lane];   // bf16x2 (cols lane*2, +1)
            uint32_t v1 = sVb[i1 * 32 + lane];
            unsigned long long vv0 = pack2(__uint_as_float(v0 << 16),
                                           __uint_as_float(v0 & 0xffff0000u));
            unsigned long long vv1 = pack2(__uint_as_float(v1 << 16),
                                           __uint_as_float(v1 & 0xffff0000u));
            a0 = fma2(pack2(e0.y, e0.y), vv0, a0);
            a1 = fma2(pack2(e1.y, e1.y), vv1, a1);
        }
        size_t o0 = ((size_t)B * 128 + qr0 + r0) * 512 + hh * 64 + lane * 2;
        store_h(o0, unpack2(a0));
        store_h(o0 + 512, unpack2(a1));
    }
}

// =====================================================================
extern "C" void kernel_launch(void* const* d_in, const int* in_sizes, int n_in,
                              void* d_out, int out_size) {
    const float* h  = (const float*)d_in[0];
    const float* Wq = (const float*)d_in[1];
    const float* Wk = (const float*)d_in[2];
    const float* Wv = (const float*)d_in[3];
    const float* Wo = (const float*)d_in[4];
    float* out = (float*)d_out;

    cudaFuncSetAttribute(gemm_mma<0>, cudaFuncAttributeMaxDynamicSharedMemorySize, GEMM_SMEM);
    cudaFuncSetAttribute(gemm_mma<1>, cudaFuncAttributeMaxDynamicSharedMemorySize, GEMM_SMEM);
    cudaFuncSetAttribute(attn2, cudaFuncAttributeMaxDynamicSharedMemorySize, ATT_SMEM);

    conv_h<<<65536, 256>>>(h);
    conv_w<<<1024, 256>>>(Wq, Wk, Wv, Wo);
    gemm_mma<0><<<dim3(12, 1024), 256, GEMM_SMEM>>>(nullptr, nullptr);
    attn2<<<16384, 256, ATT_SMEM>>>();
    gemm_mma<1><<<dim3(4, 1024), 256, GEMM_SMEM>>>(h, out);
}

// round 13
// speedup vs baseline: 1.2017x; 1.1478x over previous
#include <cuda_runtime.h>
#include <cuda_bf16.h>
#include <cstdint>

// Problem dims
#define BSZ 16
#define NV  128
#define NT  64
#define DM  512
#define HEADS 8
#define HD  64
#define TOPKN 16
#define BATT (BSZ*NT)          // 1024
#define FULLMASK 0xffffffffu

#define HN ((size_t)BSZ*NV*NT*DM)   // 67,108,864 elements
#define QKN ((size_t)BATT*HEADS*NV*HD)

// ---------- scratch (device globals; no allocation allowed) ----------
__device__ __nv_bfloat16 g_Qhi[QKN];    // [B][H][V][hd], pre-scaled by 1/8
__device__ __nv_bfloat16 g_Qlo[QKN];
__device__ __nv_bfloat16 g_Khi[QKN];
__device__ __nv_bfloat16 g_Klo[QKN];
__device__ __nv_bfloat16 g_Vb[QKN];     // [B][H][V][hd] bf16
__device__ __nv_bfloat16 g_Hhi[HN];     // h split hi  [m][k], m=(b*128+v)*64+t
__device__ __nv_bfloat16 g_Hlo[HN];
__device__ __nv_bfloat16 g_Mhi[HN];     // mixed bf16 [m][k], m=(b*64+t)*128+v
__device__ __nv_bfloat16 g_Whi[4*DM*DM];  // Wq,Wk,Wv,Wo split hi [n][k]
__device__ __nv_bfloat16 g_Wlo[4*DM*DM];

// ---------- packed f32x2 helpers ----------
__device__ __forceinline__ unsigned long long pack2(float lo, float hi) {
    unsigned long long r;
    asm("mov.b64 %0, {%1, %2};" : "=l"(r) : "f"(lo), "f"(hi));
    return r;
}
__device__ __forceinline__ float2 unpack2(unsigned long long v) {
    float2 r;
    asm("mov.b64 {%0, %1}, %2;" : "=f"(r.x), "=f"(r.y) : "l"(v));
    return r;
}
__device__ __forceinline__ unsigned long long fma2(unsigned long long a,
                                                   unsigned long long b,
                                                   unsigned long long c) {
    unsigned long long d;
    asm("fma.rn.f32x2 %0, %1, %2, %3;" : "=l"(d) : "l"(a), "l"(b), "l"(c));
    return d;
}

// ---------- misc helpers ----------
__device__ __forceinline__ uint32_t smem_u32(const void* p) {
    uint32_t a;
    asm("{ .reg .u64 t; cvta.to.shared.u64 t, %1; cvt.u32.u64 %0, t; }"
        : "=r"(a) : "l"(p));
    return a;
}
__device__ __forceinline__ void split1(float x, __nv_bfloat16& h, __nv_bfloat16& l) {
    h = __float2bfloat16(x);
    l = __float2bfloat16(x - __bfloat162float(h));
}
__device__ __forceinline__ uint32_t redux_max_u32(uint32_t v) {
    uint32_t r;
    asm volatile("redux.sync.max.u32 %0, %1, 0xffffffff;" : "=r"(r) : "r"(v));
    return r;
}
// monotonic float->uint map (order-preserving)
__device__ __forceinline__ uint32_t f2u(float x) {
    uint32_t u = __float_as_uint(x);
    return u ^ (uint32_t)(((int32_t)u >> 31) | 0x80000000);
}
__device__ __forceinline__ float u2f(uint32_t u) {
    uint32_t x = (u >> 31) ? (u ^ 0x80000000u) : ~u;
    return __uint_as_float(x);
}
__device__ __forceinline__ void csw(uint32_t& a, uint32_t& b) {  // desc compare-swap
    uint32_t hi = max(a, b), lo = min(a, b);
    a = hi; b = lo;
}

// ---------- bf16 split pre-conversion kernels ----------
__global__ void __launch_bounds__(256) conv_h(const float* __restrict__ src) {
    size_t i = ((size_t)blockIdx.x * 256 + threadIdx.x) * 4;
    float4 f = *(const float4*)(src + i);
    __nv_bfloat16 h0,l0,h1,l1,h2,l2,h3,l3;
    split1(f.x,h0,l0); split1(f.y,h1,l1); split1(f.z,h2,l2); split1(f.w,h3,l3);
    ushort4 H = { __bfloat16_as_ushort(h0), __bfloat16_as_ushort(h1),
                  __bfloat16_as_ushort(h2), __bfloat16_as_ushort(h3) };
    ushort4 L = { __bfloat16_as_ushort(l0), __bfloat16_as_ushort(l1),
                  __bfloat16_as_ushort(l2), __bfloat16_as_ushort(l3) };
    *(ushort4*)(g_Hhi + i) = H;
    *(ushort4*)(g_Hlo + i) = L;
}

__global__ void __launch_bounds__(256) conv_w(const float* __restrict__ q,
                                              const float* __restrict__ k,
                                              const float* __restrict__ v,
                                              const float* __restrict__ o) {
    size_t i4 = (size_t)blockIdx.x * 256 + threadIdx.x;
    int w = (int)(i4 >> 16);
    const float* s = (w == 0) ? q : (w == 1) ? k : (w == 2) ? v : o;
    size_t loc = (i4 & 65535) * 4;
    size_t i = i4 * 4;
    float4 f = *(const float4*)(s + loc);
    __nv_bfloat16 h0,l0,h1,l1,h2,l2,h3,l3;
    split1(f.x,h0,l0); split1(f.y,h1,l1); split1(f.z,h2,l2); split1(f.w,h3,l3);
    ushort4 H = { __bfloat16_as_ushort(h0), __bfloat16_as_ushort(h1),
                  __bfloat16_as_ushort(h2), __bfloat16_as_ushort(h3) };
    ushort4 L = { __bfloat16_as_ushort(l0), __bfloat16_as_ushort(l1),
                  __bfloat16_as_ushort(l2), __bfloat16_as_ushort(l3) };
    *(ushort4*)(g_Whi + i) = H;
    *(ushort4*)(g_Wlo + i) = L;
}

// ---------- tensor-core GEMM (128x128, 256thr, 2 CTA/SM) ----------
#define STAGE_B   32768
#define GEMM_SMEM (3*STAGE_B)   // 3-stage ring, 96KB

__device__ __forceinline__ uint32_t swz(uint32_t off) {     // 64B rows
    return off ^ (((off >> 6) & 7) << 4);
}
__device__ __forceinline__ uint32_t swz128(uint32_t off) {  // 128B rows
    return off ^ (((off >> 7) & 7) << 4);
}

#define CPA16(dst, src) \
    asm volatile("cp.async.cg.shared.global [%0], [%1], 16;" :: "r"(dst), "l"(src))
#define CPCOMMIT() asm volatile("cp.async.commit_group;" ::: "memory")
#define CPWAIT(n)  asm volatile("cp.async.wait_group %0;" :: "n"(n) : "memory")

#define LDSM4(r, a) \
    asm volatile("ldmatrix.sync.aligned.m8n8.x4.shared.b16 {%0,%1,%2,%3}, [%4];" \
        : "=r"((r)[0]),"=r"((r)[1]),"=r"((r)[2]),"=r"((r)[3]) : "r"(a))

#define MMA16816(d, a, b0, b1) \
    asm volatile("mma.sync.aligned.m16n8k16.row.col.f32.bf16.bf16.f32 " \
        "{%0,%1,%2,%3},{%4,%5,%6,%7},{%8,%9},{%0,%1,%2,%3};" \
        : "+f"((d)[0]),"+f"((d)[1]),"+f"((d)[2]),"+f"((d)[3]) \
        : "r"((a)[0]),"r"((a)[1]),"r"((a)[2]),"r"((a)[3]), "r"(b0),"r"(b1))

// MODE 0: qkv (A=g_Hhi/lo, W = weight bx>>2). Q/K: 3 products; V: 1 product.
// MODE 1: out-proj (A=g_Mhi, W = Wo_hi, 1 product, + residual)
template <int MODE>
__global__ void __launch_bounds__(256, 2) gemm_mma(
    const float* __restrict__ hres, float* __restrict__ outp)
{
    extern __shared__ char sm[];
    uint32_t sb = smem_u32(sm);
    int tid = threadIdx.x, lane = tid & 31, wid = tid >> 5;
    int bx = blockIdx.x;
    int m0 = blockIdx.y * 128;
    int wsel, n0;
    if (MODE == 0) { wsel = bx >> 2; n0 = (bx & 3) * 128; }
    else           { wsel = 3;       n0 = bx * 128; }

    // number of split products: Q/K = 3 (hi*hi + hi*lo + lo*hi); V/out = 1 (hi*hi)
    const bool full3 = (MODE == 0) && (wsel != 2);    // CTA-uniform

    const __nv_bfloat16* Ahi = (MODE == 0) ? g_Hhi : g_Mhi;
    const __nv_bfloat16* Alo = (MODE == 0) ? g_Hlo : g_Mhi;  // unused if !full3
    const __nv_bfloat16* Bhi = g_Whi + (size_t)wsel * DM * DM;
    const __nv_bfloat16* Blo = g_Wlo + (size_t)wsel * DM * DM;

    // stage slots: Ahi 0 | Alo 8192 | Bhi 16384 | Blo 24576
    auto loadc = [&](int c) {
        uint32_t stb = sb + (uint32_t)(c % 3) * STAGE_B;
        if (full3) {
#pragma unroll
            for (int i = 0; i < 8; i++) {
                int g = tid + i * 256;
                int tile = g >> 9;
                int idx = g & 511;
                int row = idx >> 2, kg = idx & 3;
                const __nv_bfloat16* src;
                if (tile == 0)      src = Ahi + (size_t)(m0 + row) * 512;
                else if (tile == 1) src = Alo + (size_t)(m0 + row) * 512;
                else if (tile == 2) src = Bhi + (size_t)(n0 + row) * 512;
                else                src = Blo + (size_t)(n0 + row) * 512;
                src += c * 32 + kg * 8;
                uint32_t dst = stb + tile * 8192 + swz((uint32_t)(row * 64 + kg * 16));
                CPA16(dst, src);
            }
        } else {
            // 1-product: only Ahi + Bhi (half the traffic)
#pragma unroll
            for (int i = 0; i < 4; i++) {
                int g = tid + i * 256;              // 0..1023
                int tile = g >> 9;                  // 0:Ahi 1:Bhi
                int idx = g & 511;
                int row = idx >> 2, kg = idx & 3;
                const __nv_bfloat16* src = (tile == 0)
                    ? Ahi + (size_t)(m0 + row) * 512
                    : Bhi + (size_t)(n0 + row) * 512;
                int slot = (tile == 0) ? 0 : 2;
                src += c * 32 + kg * 8;
                uint32_t dst = stb + slot * 8192 + swz((uint32_t)(row * 64 + kg * 16));
                CPA16(dst, src);
            }
        }
        CPCOMMIT();
    };

    int wm = wid & 3, wn = wid >> 2;      // warp tile: 32(M) x 64(N)
    float acc[64];
#pragma unroll
    for (int i = 0; i < 64; i++) acc[i] = 0.f;

    loadc(0);
    loadc(1);
    for (int c = 0; c < 16; c++) {
        if (c == 15) { CPWAIT(0); } else { CPWAIT(1); }
        __syncthreads();                  // chunk c ready; slot (c+2)%3 free
        if (c + 2 < 16) loadc(c + 2);
        uint32_t stb = sb + (uint32_t)(c % 3) * STAGE_B;
#pragma unroll
        for (int ks = 0; ks < 2; ks++) {
            uint32_t ah[2][4];
            uint32_t al[2][4] = {{0,0,0,0},{0,0,0,0}};
#pragma unroll
            for (int mt = 0; mt < 2; mt++) {
                int r = wm * 32 + mt * 16 + (lane & 15);
                uint32_t off = swz((uint32_t)(r * 64 + (ks * 16 + (lane >> 4) * 8) * 2));
                LDSM4(ah[mt], stb + off);
                if (full3) LDSM4(al[mt], stb + 8192 + off);
            }
#pragma unroll
            for (int p = 0; p < 4; p++) {
                int rr = wn * 64 + (2 * p + (lane >> 4)) * 8 + (lane & 7);
                uint32_t off = swz((uint32_t)(rr * 64 + (ks * 16 + ((lane >> 3) & 1) * 8) * 2));
                uint32_t bh[4];
                uint32_t bl[4] = {0,0,0,0};
                LDSM4(bh, stb + 16384 + off);
                if (full3) LDSM4(bl, stb + 24576 + off);
#pragma unroll
                for (int pr = 0; pr < 3; pr++) {
                    if (pr > 0 && !full3) continue;    // V / out-proj: 1 product
#pragma unroll
                    for (int mt = 0; mt < 2; mt++) {
#pragma unroll
                        for (int q = 0; q < 2; q++) {
                            float* d = acc + mt * 32 + (2 * p + q) * 4;
                            const uint32_t* a = (pr == 2) ? al[mt] : ah[mt];
                            const uint32_t* b = (pr == 1) ? bl : bh;
                            MMA16816(d, a, b[2 * q], b[2 * q + 1]);
                        }
                    }
                }
            }
        }
    }

    // ---- epilogue ----
#pragma unroll
    for (int mt = 0; mt < 2; mt++) {
#pragma unroll
        for (int half = 0; half < 2; half++) {
            int m = m0 + wm * 32 + mt * 16 + half * 8 + (lane >> 2);
            if (MODE == 0) {
                int b = m >> 13, v = (m >> 6) & 127, t = m & 63;
                int head = (n0 >> 6) + wn;
                size_t rb = (((size_t)(b * 64 + t) * 8 + head) * 128 + v) * 64
                            + (lane & 3) * 2;
#pragma unroll
                for (int nt = 0; nt < 8; nt++) {
                    int base = mt * 32 + nt * 4 + half * 2;
                    float2 val = make_float2(acc[base], acc[base + 1]);
                    size_t g = rb + nt * 8;
                    if (wsel == 2) {
                        ushort2 V2 = { __bfloat16_as_ushort(__float2bfloat16(val.x)),
                                       __bfloat16_as_ushort(__float2bfloat16(val.y)) };
                        *(ushort2*)(g_Vb + g) = V2;
                    } else {
                        if (wsel == 0) { val.x *= 0.125f; val.y *= 0.125f; }
                        __nv_bfloat16 h0, l0, h1, l1;
                        split1(val.x, h0, l0);
                        split1(val.y, h1, l1);
                        ushort2 H = { __bfloat16_as_ushort(h0), __bfloat16_as_ushort(h1) };
                        ushort2 L = { __bfloat16_as_ushort(l0), __bfloat16_as_ushort(l1) };
                        if (wsel == 0) {
                            *(ushort2*)(g_Qhi + g) = H;
                            *(ushort2*)(g_Qlo + g) = L;
                        } else {
                            *(ushort2*)(g_Khi + g) = H;
                            *(ushort2*)(g_Klo + g) = L;
                        }
                    }
                }
            } else {
                int Bi = m >> 7, v = m & 127;
                int b = Bi >> 6, t = Bi & 63;
                size_t dbase = (((size_t)b * 128 + v) * 64 + t) * 512
                               + n0 + wn * 64 + (lane & 3) * 2;
#pragma unroll
                for (int nt = 0; nt < 8; nt++) {
                    int base = mt * 32 + nt * 4 + half * 2;
                    float2 val = make_float2(acc[base], acc[base + 1]);
                    size_t d = dbase + nt * 8;
                    float2 hv = *(const float2*)&hres[d];
                    val.x += hv.x; val.y += hv.y;
                    *(float2*)&outp[d] = val;
                }
            }
        }
    }
}

// =====================================================================
// Attention v7 (round-12 proven): 64 q-rows per CTA, bf16 V, 72KB smem,
// 3 CTA/SM. tensor-core scores + sorted-tournament top-16 + sparse AV.
// =====================================================================
#define AOFF_QHI 0                // [64][128B]  8KB
#define AOFF_QLO 8192             // 8KB
#define AOFF_KHI 16384            // [128][128B] 16KB
#define AOFF_KLO 32768            // 16KB  (Q/K end 49152)
#define AOFF_S   0                // overlays Q/KHI: fp32 [64][128] = 32KB
#define AOFF_V   49152            // bf16 [128][64] = 16KB
#define AOFF_P   65536            // float2 [64][16] = 8KB  (idx bits, p)
#define ATT_SMEM 73728

// XOR bank-swizzled S index ([64][128] fp32)
__device__ __forceinline__ int sidx(int r, int c) {
    return r * 128 + (c ^ ((r & 7) << 2));
}

__device__ __forceinline__ void store_h(size_t idx, float2 v) {
    ushort2 H = { __bfloat16_as_ushort(__float2bfloat16(v.x)),
                  __bfloat16_as_ushort(__float2bfloat16(v.y)) };
    *(ushort2*)(g_Mhi + idx) = H;
}

__global__ void __launch_bounds__(256, 3) attn2() {
    extern __shared__ char sm[];
    uint32_t sb = smem_u32(sm);
    float* sS = (float*)(sm + AOFF_S);
    float2* sP = (float2*)(sm + AOFF_P);

    int tid = threadIdx.x, lane = tid & 31, wid = tid >> 5;
    int bx = blockIdx.x;                 // ((B*8+head)<<1) | half
    int bh = bx >> 1;
    int qr0 = (bx & 1) * 64;             // q-row offset within the 128
    size_t base = (size_t)bh * 8192;     // 128*64

    // zero compacted-P arrays (idx bits 0 = row 0, p 0 -> harmless)
    for (int i = tid; i < 1024; i += 256) sP[i] = make_float2(0.f, 0.f);

    // ---- async loads: Q half (64 rows), K full, V bf16 ----
#pragma unroll
    for (int i = 0; i < 2; i++) {
        int g = tid + i * 256;           // 0..511 (64 rows x 8 chunks)
        int row = g >> 3, kg = g & 7;
        uint32_t doff = swz128((uint32_t)(row * 128 + kg * 16));
        CPA16(sb + AOFF_QHI + doff, g_Qhi + base + (size_t)(qr0 + row) * 64 + kg * 8);
        CPA16(sb + AOFF_QLO + doff, g_Qlo + base + (size_t)(qr0 + row) * 64 + kg * 8);
    }
#pragma unroll
    for (int i = 0; i < 4; i++) {
        int g = tid + i * 256;           // 0..1023 (128 rows x 8 chunks)
        int row = g >> 3, kg = g & 7;
        uint32_t doff = swz128((uint32_t)(row * 128 + kg * 16));
        CPA16(sb + AOFF_KHI + doff, g_Khi + base + (size_t)row * 64 + kg * 8);
        CPA16(sb + AOFF_KLO + doff, g_Klo + base + (size_t)row * 64 + kg * 8);
    }
#pragma unroll
    for (int i = 0; i < 4; i++) {
        int g = tid + i * 256;           // 0..1023 chunks of 16B (16KB)
        CPA16(sb + AOFF_V + g * 16, g_Vb + base + g * 8);
    }
    CPCOMMIT();
    CPWAIT(0);
    __syncthreads();

    // ---- S = Q @ K^T via mma (3-product split). warp tile 32(M) x 32(N) ----
    {
        int wm = wid & 1, wn = wid >> 1;
        float acc[32];
#pragma unroll
        for (int i = 0; i < 32; i++) acc[i] = 0.f;
#pragma unroll
        for (int kt = 0; kt < 4; kt++) {
            uint32_t ah[2][4], al[2][4];
#pragma unroll
            for (int mt = 0; mt < 2; mt++) {
                int r = wm * 32 + mt * 16 + (lane & 15);
                uint32_t off = swz128((uint32_t)(r * 128 + (kt * 16 + (lane >> 4) * 8) * 2));
                LDSM4(ah[mt], sb + AOFF_QHI + off);
                LDSM4(al[mt], sb + AOFF_QLO + off);
            }
#pragma unroll
            for (int p = 0; p < 2; p++) {
                int rr = wn * 32 + (2 * p + (lane >> 4)) * 8 + (lane & 7);
                uint32_t off = swz128((uint32_t)(rr * 128 + (kt * 16 + ((lane >> 3) & 1) * 8) * 2));
                uint32_t bh4[4], bl4[4];
                LDSM4(bh4, sb + AOFF_KHI + off);
                LDSM4(bl4, sb + AOFF_KLO + off);
#pragma unroll
                for (int pr = 0; pr < 3; pr++) {
#pragma unroll
                    for (int mt = 0; mt < 2; mt++) {
#pragma unroll
                        for (int q = 0; q < 2; q++) {
                            float* d = acc + mt * 16 + (2 * p + q) * 4;
                            const uint32_t* a = (pr == 2) ? al[mt] : ah[mt];
                            const uint32_t* b = (pr == 1) ? bl4 : bh4;
                            MMA16816(d, a, b[2 * q], b[2 * q + 1]);
                        }
                    }
                }
            }
        }
        __syncthreads();   // all warps done reading Q/K before S overwrites them
        // store S to overlaid SMEM [64][128] with XOR swizzle
#pragma unroll
        for (int mt = 0; mt < 2; mt++) {
#pragma unroll
            for (int half = 0; half < 2; half++) {
                int r = wm * 32 + mt * 16 + half * 8 + (lane >> 2);
#pragma unroll
                for (int nt = 0; nt < 4; nt++) {
                    int col = wn * 32 + nt * 8 + (lane & 3) * 2;
                    int bi = mt * 16 + nt * 4 + half * 2;
                    *(float2*)&sS[sidx(r, col)] = make_float2(acc[bi], acc[bi + 1]);
                }
            }
        }
    }
    __syncthreads();

    // ---- top-16 (sorted tournament) + softmax, warp per 2 rows ----
    for (int i = 0; i < 4; i++) {
        int r0 = wid * 8 + 2 * i;
        int r1 = r0 + 1;
        float4 f0 = *(float4*)&sS[sidx(r0, lane * 4)];
        float4 f1 = *(float4*)&sS[sidx(r1, lane * 4)];
        float fa0[4] = { f0.x, f0.y, f0.z, f0.w };
        float fa1[4] = { f1.x, f1.y, f1.z, f1.w };
        uint32_t uo0[4], uo1[4], u0[4], u1[4];
#pragma unroll
        for (int e = 0; e < 4; e++) {
            uo0[e] = u0[e] = f2u(fa0[e]);
            uo1[e] = u1[e] = f2u(fa1[e]);
        }
        // per-lane descending sort of 4 values (sorting network)
        csw(u0[0], u0[2]); csw(u0[1], u0[3]);
        csw(u0[0], u0[1]); csw(u0[2], u0[3]); csw(u0[1], u0[2]);
        csw(u1[0], u1[2]); csw(u1[1], u1[3]);
        csw(u1[0], u1[1]); csw(u1[2], u1[3]); csw(u1[1], u1[2]);

        float rm0 = 0.f, rm1 = 0.f;
        uint32_t th0 = 0, th1 = 0;
#pragma unroll 1
        for (int it = 0; it < TOPKN; it++) {
            uint32_t g0 = redux_max_u32(u0[0]);
            uint32_t g1 = redux_max_u32(u1[0]);
            if (it == 0) { rm0 = u2f(g0); rm1 = u2f(g1); }
            th0 = g0; th1 = g1;
            bool t0 = (u0[0] == g0);
            bool t1 = (u1[0] == g1);
            u0[0] = t0 ? u0[1] : u0[0];
            u0[1] = t0 ? u0[2] : u0[1];
            u0[2] = t0 ? u0[3] : u0[2];
            u0[3] = t0 ? 0u    : u0[3];
            u1[0] = t1 ? u1[1] : u1[0];
            u1[1] = t1 ? u1[2] : u1[1];
            u1[2] = t1 ? u1[3] : u1[2];
            u1[3] = t1 ? 0u    : u1[3];
        }
        float p0[4], p1[4];
        float s0 = 0.f, s1 = 0.f;
#pragma unroll
        for (int e = 0; e < 4; e++) {
            p0[e] = (uo0[e] >= th0) ? __expf(fa0[e] - rm0) : 0.f;
            p1[e] = (uo1[e] >= th1) ? __expf(fa1[e] - rm1) : 0.f;
            s0 += p0[e]; s1 += p1[e];
        }
#pragma unroll
        for (int o = 16; o; o >>= 1) {
            s0 += __shfl_xor_sync(FULLMASK, s0, o);
            s1 += __shfl_xor_sync(FULLMASK, s1, o);
        }
        float inv0 = 1.0f / s0, inv1 = 1.0f / s1;
        // compact packed (idx, p) into 16-entry float2 lists
        int bc0 = 0, bc1 = 0;
#pragma unroll
        for (int e = 0; e < 4; e++) {
            uint32_t b0 = __ballot_sync(FULLMASK, p0[e] > 0.f);
            uint32_t b1 = __ballot_sync(FULLMASK, p1[e] > 0.f);
            uint32_t lt = (1u << lane) - 1u;
            if (p0[e] > 0.f) {
                int pos = bc0 + __popc(b0 & lt);
                if (pos < 16)
                    sP[r0 * 16 + pos] =
                        make_float2(__int_as_float(lane * 4 + e), p0[e] * inv0);
            }
            if (p1[e] > 0.f) {
                int pos = bc1 + __popc(b1 & lt);
                if (pos < 16)
                    sP[r1 * 16 + pos] =
                        make_float2(__int_as_float(lane * 4 + e), p1[e] * inv1);
            }
            bc0 += __popc(b0);
            bc1 += __popc(b1);
        }
    }
    __syncthreads();

    // ---- sparse AV over bf16 V: mixed[r] = sum_j p_j * V[idx_j] ----
    int B = bh >> 3, hh = bh & 7;
    const uint32_t* sVb = (const uint32_t*)(sm + AOFF_V);   // bf16x2 units
    for (int i = 0; i < 4; i++) {
        int r0 = wid * 8 + 2 * i;
        int r1 = r0 + 1;
        unsigned long long a0 = 0, a1 = 0;
#pragma unroll
        for (int j = 0; j < 16; j++) {
            float2 e0 = sP[r0 * 16 + j];
            float2 e1 = sP[r1 * 16 + j];
            int i0 = __float_as_int(e0.x);
            int i1 = __float_as_int(e1.x);
            uint32_t v0 = sVb[i0 * 32 + lane];   // bf16x2 (cols lane*2, +1)
            uint32_t v1 = sVb[i1 * 32 + lane];
            unsigned long long vv0 = pack2(__uint_as_float(v0 << 16),
                                           __uint_as_float(v0 & 0xffff0000u));
            unsigned long long vv1 = pack2(__uint_as_float(v1 << 16),
                                           __uint_as_float(v1 & 0xffff0000u));
            a0 = fma2(pack2(e0.y, e0.y), vv0, a0);
            a1 = fma2(pack2(e1.y, e1.y), vv1, a1);
        }
        size_t o0 = ((size_t)B * 128 + qr0 + r0) * 512 + hh * 64 + lane * 2;
        store_h(o0, unpack2(a0));
        store_h(o0 + 512, unpack2(a1));
    }
}

// =====================================================================
extern "C" void kernel_launch(void* const* d_in, const int* in_sizes, int n_in,
                              void* d_out, int out_size) {
    const float* h  = (const float*)d_in[0];
    const float* Wq = (const float*)d_in[1];
    const float* Wk = (const float*)d_in[2];
    const float* Wv = (const float*)d_in[3];
    const float* Wo = (const float*)d_in[4];
    float* out = (float*)d_out;

    cudaFuncSetAttribute(gemm_mma<0>, cudaFuncAttributeMaxDynamicSharedMemorySize, GEMM_SMEM);
    cudaFuncSetAttribute(gemm_mma<1>, cudaFuncAttributeMaxDynamicSharedMemorySize, GEMM_SMEM);
    cudaFuncSetAttribute(attn2, cudaFuncAttributeMaxDynamicSharedMemorySize, ATT_SMEM);

    conv_h<<<65536, 256>>>(h);
    conv_w<<<1024, 256>>>(Wq, Wk, Wv, Wo);
    gemm_mma<0><<<dim3(12, 1024), 256, GEMM_SMEM>>>(nullptr, nullptr);
    attn2<<<16384, 256, ATT_SMEM>>>();
    gemm_mma<1><<<dim3(4, 1024), 256, GEMM_SMEM>>>(h, out);
}

// round 14
// speedup vs baseline: 1.2122x; 1.0088x over previous
#include <cuda_runtime.h>
#include <cuda_bf16.h>
#include <cstdint>

// Problem dims
#define BSZ 16
#define NV  128
#define NT  64
#define DM  512
#define HEADS 8
#define HD  64
#define TOPKN 16
#define BATT (BSZ*NT)          // 1024
#define FULLMASK 0xffffffffu

#define HN ((size_t)BSZ*NV*NT*DM)   // 67,108,864 elements
#define QKN ((size_t)BATT*HEADS*NV*HD)

// ---------- scratch (device globals; no allocation allowed) ----------
__device__ __nv_bfloat16 g_Qhi[QKN];    // [B][H][V][hd], pre-scaled by 1/8
__device__ __nv_bfloat16 g_Qlo[QKN];
__device__ __nv_bfloat16 g_Khi[QKN];
__device__ __nv_bfloat16 g_Klo[QKN];
__device__ __nv_bfloat16 g_Vb[QKN];     // [B][H][V][hd] bf16
__device__ __nv_bfloat16 g_Hhi[HN];     // h split hi  [m][k], m=(b*128+v)*64+t
__device__ __nv_bfloat16 g_Hlo[HN];
__device__ __nv_bfloat16 g_Mhi[HN];     // mixed bf16 [m][k], m=(b*64+t)*128+v
__device__ __nv_bfloat16 g_Whi[4*DM*DM];  // Wq,Wk,Wv,Wo split hi [n][k]
__device__ __nv_bfloat16 g_Wlo[4*DM*DM];

// ---------- packed f32x2 helpers ----------
__device__ __forceinline__ unsigned long long pack2(float lo, float hi) {
    unsigned long long r;
    asm("mov.b64 %0, {%1, %2};" : "=l"(r) : "f"(lo), "f"(hi));
    return r;
}
__device__ __forceinline__ float2 unpack2(unsigned long long v) {
    float2 r;
    asm("mov.b64 {%0, %1}, %2;" : "=f"(r.x), "=f"(r.y) : "l"(v));
    return r;
}
__device__ __forceinline__ unsigned long long fma2(unsigned long long a,
                                                   unsigned long long b,
                                                   unsigned long long c) {
    unsigned long long d;
    asm("fma.rn.f32x2 %0, %1, %2, %3;" : "=l"(d) : "l"(a), "l"(b), "l"(c));
    return d;
}

// ---------- misc helpers ----------
__device__ __forceinline__ uint32_t smem_u32(const void* p) {
    uint32_t a;
    asm("{ .reg .u64 t; cvta.to.shared.u64 t, %1; cvt.u32.u64 %0, t; }"
        : "=r"(a) : "l"(p));
    return a;
}
__device__ __forceinline__ void split1(float x, __nv_bfloat16& h, __nv_bfloat16& l) {
    h = __float2bfloat16(x);
    l = __float2bfloat16(x - __bfloat162float(h));
}
__device__ __forceinline__ uint32_t redux_max_u32(uint32_t v) {
    uint32_t r;
    asm volatile("redux.sync.max.u32 %0, %1, 0xffffffff;" : "=r"(r) : "r"(v));
    return r;
}
// monotonic float->uint map (order-preserving)
__device__ __forceinline__ uint32_t f2u(float x) {
    uint32_t u = __float_as_uint(x);
    return u ^ (uint32_t)(((int32_t)u >> 31) | 0x80000000);
}
__device__ __forceinline__ float u2f(uint32_t u) {
    uint32_t x = (u >> 31) ? (u ^ 0x80000000u) : ~u;
    return __uint_as_float(x);
}
__device__ __forceinline__ void csw(uint32_t& a, uint32_t& b) {  // desc compare-swap
    uint32_t hi = max(a, b), lo = min(a, b);
    a = hi; b = lo;
}

// ---------- bf16 split pre-conversion kernels ----------
__global__ void __launch_bounds__(256) conv_h(const float* __restrict__ src) {
    size_t i = ((size_t)blockIdx.x * 256 + threadIdx.x) * 4;
    float4 f = *(const float4*)(src + i);
    __nv_bfloat16 h0,l0,h1,l1,h2,l2,h3,l3;
    split1(f.x,h0,l0); split1(f.y,h1,l1); split1(f.z,h2,l2); split1(f.w,h3,l3);
    ushort4 H = { __bfloat16_as_ushort(h0), __bfloat16_as_ushort(h1),
                  __bfloat16_as_ushort(h2), __bfloat16_as_ushort(h3) };
    ushort4 L = { __bfloat16_as_ushort(l0), __bfloat16_as_ushort(l1),
                  __bfloat16_as_ushort(l2), __bfloat16_as_ushort(l3) };
    *(ushort4*)(g_Hhi + i) = H;
    *(ushort4*)(g_Hlo + i) = L;
}

__global__ void __launch_bounds__(256) conv_w(const float* __restrict__ q,
                                              const float* __restrict__ k,
                                              const float* __restrict__ v,
                                              const float* __restrict__ o) {
    size_t i4 = (size_t)blockIdx.x * 256 + threadIdx.x;
    int w = (int)(i4 >> 16);
    const float* s = (w == 0) ? q : (w == 1) ? k : (w == 2) ? v : o;
    size_t loc = (i4 & 65535) * 4;
    size_t i = i4 * 4;
    float4 f = *(const float4*)(s + loc);
    __nv_bfloat16 h0,l0,h1,l1,h2,l2,h3,l3;
    split1(f.x,h0,l0); split1(f.y,h1,l1); split1(f.z,h2,l2); split1(f.w,h3,l3);
    ushort4 H = { __bfloat16_as_ushort(h0), __bfloat16_as_ushort(h1),
                  __bfloat16_as_ushort(h2), __bfloat16_as_ushort(h3) };
    ushort4 L = { __bfloat16_as_ushort(l0), __bfloat16_as_ushort(l1),
                  __bfloat16_as_ushort(l2), __bfloat16_as_ushort(l3) };
    *(ushort4*)(g_Whi + i) = H;
    *(ushort4*)(g_Wlo + i) = L;
}

// ---------- tensor-core GEMM (round-13 proven: 128x128, 256thr, 2 CTA/SM) ----------
#define STAGE_B   32768
#define GEMM_SMEM (3*STAGE_B)   // 3-stage ring, 96KB

__device__ __forceinline__ uint32_t swz(uint32_t off) {     // 64B rows
    return off ^ (((off >> 6) & 7) << 4);
}
__device__ __forceinline__ uint32_t swz128(uint32_t off) {  // 128B rows
    return off ^ (((off >> 7) & 7) << 4);
}

#define CPA16(dst, src) \
    asm volatile("cp.async.cg.shared.global [%0], [%1], 16;" :: "r"(dst), "l"(src))
#define CPCOMMIT() asm volatile("cp.async.commit_group;" ::: "memory")
#define CPWAIT(n)  asm volatile("cp.async.wait_group %0;" :: "n"(n) : "memory")

#define LDSM4(r, a) \
    asm volatile("ldmatrix.sync.aligned.m8n8.x4.shared.b16 {%0,%1,%2,%3}, [%4];" \
        : "=r"((r)[0]),"=r"((r)[1]),"=r"((r)[2]),"=r"((r)[3]) : "r"(a))

#define MMA16816(d, a, b0, b1) \
    asm volatile("mma.sync.aligned.m16n8k16.row.col.f32.bf16.bf16.f32 " \
        "{%0,%1,%2,%3},{%4,%5,%6,%7},{%8,%9},{%0,%1,%2,%3};" \
        : "+f"((d)[0]),"+f"((d)[1]),"+f"((d)[2]),"+f"((d)[3]) \
        : "r"((a)[0]),"r"((a)[1]),"r"((a)[2]),"r"((a)[3]), "r"(b0),"r"(b1))

// MODE 0: qkv (A=g_Hhi/lo, W = weight bx>>2). Q/K: 3 products; V: 1 product.
// MODE 1: out-proj (A=g_Mhi, W = Wo_hi, 1 product, + residual)
template <int MODE>
__global__ void __launch_bounds__(256, 2) gemm_mma(
    const float* __restrict__ hres, float* __restrict__ outp)
{
    extern __shared__ char sm[];
    uint32_t sb = smem_u32(sm);
    int tid = threadIdx.x, lane = tid & 31, wid = tid >> 5;
    int bx = blockIdx.x;
    int m0 = blockIdx.y * 128;
    int wsel, n0;
    if (MODE == 0) { wsel = bx >> 2; n0 = (bx & 3) * 128; }
    else           { wsel = 3;       n0 = bx * 128; }

    const bool full3 = (MODE == 0) && (wsel != 2);    // CTA-uniform

    const __nv_bfloat16* Ahi = (MODE == 0) ? g_Hhi : g_Mhi;
    const __nv_bfloat16* Alo = (MODE == 0) ? g_Hlo : g_Mhi;  // unused if !full3
    const __nv_bfloat16* Bhi = g_Whi + (size_t)wsel * DM * DM;
    const __nv_bfloat16* Blo = g_Wlo + (size_t)wsel * DM * DM;

    auto loadc = [&](int c) {
        uint32_t stb = sb + (uint32_t)(c % 3) * STAGE_B;
        if (full3) {
#pragma unroll
            for (int i = 0; i < 8; i++) {
                int g = tid + i * 256;
                int tile = g >> 9;
                int idx = g & 511;
                int row = idx >> 2, kg = idx & 3;
                const __nv_bfloat16* src;
                if (tile == 0)      src = Ahi + (size_t)(m0 + row) * 512;
                else if (tile == 1) src = Alo + (size_t)(m0 + row) * 512;
                else if (tile == 2) src = Bhi + (size_t)(n0 + row) * 512;
                else                src = Blo + (size_t)(n0 + row) * 512;
                src += c * 32 + kg * 8;
                uint32_t dst = stb + tile * 8192 + swz((uint32_t)(row * 64 + kg * 16));
                CPA16(dst, src);
            }
        } else {
#pragma unroll
            for (int i = 0; i < 4; i++) {
                int g = tid + i * 256;              // 0..1023
                int tile = g >> 9;                  // 0:Ahi 1:Bhi
                int idx = g & 511;
                int row = idx >> 2, kg = idx & 3;
                const __nv_bfloat16* src = (tile == 0)
                    ? Ahi + (size_t)(m0 + row) * 512
                    : Bhi + (size_t)(n0 + row) * 512;
                int slot = (tile == 0) ? 0 : 2;
                src += c * 32 + kg * 8;
                uint32_t dst = stb + slot * 8192 + swz((uint32_t)(row * 64 + kg * 16));
                CPA16(dst, src);
            }
        }
        CPCOMMIT();
    };

    int wm = wid & 3, wn = wid >> 2;      // warp tile: 32(M) x 64(N)
    float acc[64];
#pragma unroll
    for (int i = 0; i < 64; i++) acc[i] = 0.f;

    loadc(0);
    loadc(1);
    for (int c = 0; c < 16; c++) {
        if (c == 15) { CPWAIT(0); } else { CPWAIT(1); }
        __syncthreads();                  // chunk c ready; slot (c+2)%3 free
        if (c + 2 < 16) loadc(c + 2);
        uint32_t stb = sb + (uint32_t)(c % 3) * STAGE_B;
#pragma unroll
        for (int ks = 0; ks < 2; ks++) {
            uint32_t ah[2][4];
            uint32_t al[2][4] = {{0,0,0,0},{0,0,0,0}};
#pragma unroll
            for (int mt = 0; mt < 2; mt++) {
                int r = wm * 32 + mt * 16 + (lane & 15);
                uint32_t off = swz((uint32_t)(r * 64 + (ks * 16 + (lane >> 4) * 8) * 2));
                LDSM4(ah[mt], stb + off);
                if (full3) LDSM4(al[mt], stb + 8192 + off);
            }
#pragma unroll
            for (int p = 0; p < 4; p++) {
                int rr = wn * 64 + (2 * p + (lane >> 4)) * 8 + (lane & 7);
                uint32_t off = swz((uint32_t)(rr * 64 + (ks * 16 + ((lane >> 3) & 1) * 8) * 2));
                uint32_t bh[4];
                uint32_t bl[4] = {0,0,0,0};
                LDSM4(bh, stb + 16384 + off);
                if (full3) LDSM4(bl, stb + 24576 + off);
#pragma unroll
                for (int pr = 0; pr < 3; pr++) {
                    if (pr > 0 && !full3) continue;    // V / out-proj: 1 product
#pragma unroll
                    for (int mt = 0; mt < 2; mt++) {
#pragma unroll
                        for (int q = 0; q < 2; q++) {
                            float* d = acc + mt * 32 + (2 * p + q) * 4;
                            const uint32_t* a = (pr == 2) ? al[mt] : ah[mt];
                            const uint32_t* b = (pr == 1) ? bl : bh;
                            MMA16816(d, a, b[2 * q], b[2 * q + 1]);
                        }
                    }
                }
            }
        }
    }

    // ---- epilogue ----
#pragma unroll
    for (int mt = 0; mt < 2; mt++) {
#pragma unroll
        for (int half = 0; half < 2; half++) {
            int m = m0 + wm * 32 + mt * 16 + half * 8 + (lane >> 2);
            if (MODE == 0) {
                int b = m >> 13, v = (m >> 6) & 127, t = m & 63;
                int head = (n0 >> 6) + wn;
                size_t rb = (((size_t)(b * 64 + t) * 8 + head) * 128 + v) * 64
                            + (lane & 3) * 2;
#pragma unroll
                for (int nt = 0; nt < 8; nt++) {
                    int base = mt * 32 + nt * 4 + half * 2;
                    float2 val = make_float2(acc[base], acc[base + 1]);
                    size_t g = rb + nt * 8;
                    if (wsel == 2) {
                        ushort2 V2 = { __bfloat16_as_ushort(__float2bfloat16(val.x)),
                                       __bfloat16_as_ushort(__float2bfloat16(val.y)) };
                        *(ushort2*)(g_Vb + g) = V2;
                    } else {
                        if (wsel == 0) { val.x *= 0.125f; val.y *= 0.125f; }
                        __nv_bfloat16 h0, l0, h1, l1;
                        split1(val.x, h0, l0);
                        split1(val.y, h1, l1);
                        ushort2 H = { __bfloat16_as_ushort(h0), __bfloat16_as_ushort(h1) };
                        ushort2 L = { __bfloat16_as_ushort(l0), __bfloat16_as_ushort(l1) };
                        if (wsel == 0) {
                            *(ushort2*)(g_Qhi + g) = H;
                            *(ushort2*)(g_Qlo + g) = L;
                        } else {
                            *(ushort2*)(g_Khi + g) = H;
                            *(ushort2*)(g_Klo + g) = L;
                        }
                    }
                }
            } else {
                int Bi = m >> 7, v = m & 127;
                int b = Bi >> 6, t = Bi & 63;
                size_t dbase = (((size_t)b * 128 + v) * 64 + t) * 512
                               + n0 + wn * 64 + (lane & 3) * 2;
#pragma unroll
                for (int nt = 0; nt < 8; nt++) {
                    int base = mt * 32 + nt * 4 + half * 2;
                    float2 val = make_float2(acc[base], acc[base + 1]);
                    size_t d = dbase + nt * 8;
                    float2 hv = *(const float2*)&hres[d];
                    val.x += hv.x; val.y += hv.y;
                    *(float2*)&outp[d] = val;
                }
            }
        }
    }
}

// =====================================================================
// Attention v8: 32 q-rows per CTA (grid 32768), 56KB smem, 4 CTA/SM.
// tensor-core scores + sorted-tournament top-16 + sparse AV.
// =====================================================================
#define A2_QHI 0                // [32][128B]  4KB
#define A2_QLO 4096             // 4KB
#define A2_KHI 8192             // [128][128B] 16KB
#define A2_KLO 24576            // 16KB (K ends 40960)
#define A2_V   40960            // bf16 [128][64] = 16KB (ends 57344)
#define A2_S   0                // overlays Q + KHI[0:8K]: fp32 [32][128] = 16KB
#define A2_P   16384            // overlays KHI[8K:12K]: float2 [32][16] = 4KB
#define ATT_SMEM 57344

// XOR bank-swizzled S index ([32][128] fp32)
__device__ __forceinline__ int sidx(int r, int c) {
    return r * 128 + (c ^ ((r & 7) << 2));
}

__device__ __forceinline__ void store_h(size_t idx, float2 v) {
    ushort2 H = { __bfloat16_as_ushort(__float2bfloat16(v.x)),
                  __bfloat16_as_ushort(__float2bfloat16(v.y)) };
    *(ushort2*)(g_Mhi + idx) = H;
}

__global__ void __launch_bounds__(256, 4) attn2() {
    extern __shared__ char sm[];
    uint32_t sb = smem_u32(sm);
    float* sS = (float*)(sm + A2_S);
    float2* sP = (float2*)(sm + A2_P);

    int tid = threadIdx.x, lane = tid & 31, wid = tid >> 5;
    int bx = blockIdx.x;                 // ((B*8+head)<<2) | quarter
    int bh = bx >> 2;
    int qr0 = (bx & 3) * 32;             // q-row offset within the 128
    size_t base = (size_t)bh * 8192;     // 128*64

    // ---- async loads: Q quarter (32 rows), K full, V bf16 ----
    {
        int g = tid;                     // 0..255 (32 rows x 8 chunks)
        int row = g >> 3, kg = g & 7;
        uint32_t doff = swz128((uint32_t)(row * 128 + kg * 16));
        CPA16(sb + A2_QHI + doff, g_Qhi + base + (size_t)(qr0 + row) * 64 + kg * 8);
        CPA16(sb + A2_QLO + doff, g_Qlo + base + (size_t)(qr0 + row) * 64 + kg * 8);
    }
#pragma unroll
    for (int i = 0; i < 4; i++) {
        int g = tid + i * 256;           // 0..1023 (128 rows x 8 chunks)
        int row = g >> 3, kg = g & 7;
        uint32_t doff = swz128((uint32_t)(row * 128 + kg * 16));
        CPA16(sb + A2_KHI + doff, g_Khi + base + (size_t)row * 64 + kg * 8);
        CPA16(sb + A2_KLO + doff, g_Klo + base + (size_t)row * 64 + kg * 8);
    }
#pragma unroll
    for (int i = 0; i < 4; i++) {
        int g = tid + i * 256;           // 0..1023 chunks of 16B (16KB)
        CPA16(sb + A2_V + g * 16, g_Vb + base + g * 8);
    }
    CPCOMMIT();
    CPWAIT(0);
    __syncthreads();

    // ---- S = Q @ K^T via mma (3-product split). warp tile 32(M) x 16(N) ----
    {
        float acc[16];
#pragma unroll
        for (int i = 0; i < 16; i++) acc[i] = 0.f;
#pragma unroll
        for (int kt = 0; kt < 4; kt++) {
            uint32_t ah[2][4], al[2][4];
#pragma unroll
            for (int mt = 0; mt < 2; mt++) {
                int r = mt * 16 + (lane & 15);
                uint32_t off = swz128((uint32_t)(r * 128 + (kt * 16 + (lane >> 4) * 8) * 2));
                LDSM4(ah[mt], sb + A2_QHI + off);
                LDSM4(al[mt], sb + A2_QLO + off);
            }
            {
                int rr = wid * 16 + (lane >> 4) * 8 + (lane & 7);
                uint32_t off = swz128((uint32_t)(rr * 128 + (kt * 16 + ((lane >> 3) & 1) * 8) * 2));
                uint32_t bh4[4], bl4[4];
                LDSM4(bh4, sb + A2_KHI + off);
                LDSM4(bl4, sb + A2_KLO + off);
#pragma unroll
                for (int pr = 0; pr < 3; pr++) {
#pragma unroll
                    for (int mt = 0; mt < 2; mt++) {
#pragma unroll
                        for (int q = 0; q < 2; q++) {
                            float* d = acc + mt * 8 + q * 4;
                            const uint32_t* a = (pr == 2) ? al[mt] : ah[mt];
                            const uint32_t* b = (pr == 1) ? bl4 : bh4;
                            MMA16816(d, a, b[2 * q], b[2 * q + 1]);
                        }
                    }
                }
            }
        }
        __syncthreads();   // all warps done reading Q/K before S/P overwrite them
        // store S to overlaid SMEM [32][128] with XOR swizzle
#pragma unroll
        for (int mt = 0; mt < 2; mt++) {
#pragma unroll
            for (int half = 0; half < 2; half++) {
                int r = mt * 16 + half * 8 + (lane >> 2);
#pragma unroll
                for (int nt = 0; nt < 2; nt++) {
                    int col = wid * 16 + nt * 8 + (lane & 3) * 2;
                    int bi = mt * 8 + nt * 4 + half * 2;
                    *(float2*)&sS[sidx(r, col)] = make_float2(acc[bi], acc[bi + 1]);
                }
            }
        }
        // zero compacted-P lists (overlays dead KHI region; safe after sync)
        for (int i = tid; i < 512; i += 256) sP[i] = make_float2(0.f, 0.f);
    }
    __syncthreads();

    // ---- top-16 (sorted tournament) + softmax, warp per 2 rows x 2 iters ----
    for (int i = 0; i < 2; i++) {
        int r0 = wid * 4 + 2 * i;
        int r1 = r0 + 1;
        float4 f0 = *(float4*)&sS[sidx(r0, lane * 4)];
        float4 f1 = *(float4*)&sS[sidx(r1, lane * 4)];
        float fa0[4] = { f0.x, f0.y, f0.z, f0.w };
        float fa1[4] = { f1.x, f1.y, f1.z, f1.w };
        uint32_t uo0[4], uo1[4], u0[4], u1[4];
#pragma unroll
        for (int e = 0; e < 4; e++) {
            uo0[e] = u0[e] = f2u(fa0[e]);
            uo1[e] = u1[e] = f2u(fa1[e]);
        }
        // per-lane descending sort of 4 values (sorting network)
        csw(u0[0], u0[2]); csw(u0[1], u0[3]);
        csw(u0[0], u0[1]); csw(u0[2], u0[3]); csw(u0[1], u0[2]);
        csw(u1[0], u1[2]); csw(u1[1], u1[3]);
        csw(u1[0], u1[1]); csw(u1[2], u1[3]); csw(u1[1], u1[2]);

        float rm0 = 0.f, rm1 = 0.f;
        uint32_t th0 = 0, th1 = 0;
#pragma unroll 1
        for (int it = 0; it < TOPKN; it++) {
            uint32_t g0 = redux_max_u32(u0[0]);
            uint32_t g1 = redux_max_u32(u1[0]);
            if (it == 0) { rm0 = u2f(g0); rm1 = u2f(g1); }
            th0 = g0; th1 = g1;
            bool t0 = (u0[0] == g0);
            bool t1 = (u1[0] == g1);
            u0[0] = t0 ? u0[1] : u0[0];
            u0[1] = t0 ? u0[2] : u0[1];
            u0[2] = t0 ? u0[3] : u0[2];
            u0[3] = t0 ? 0u    : u0[3];
            u1[0] = t1 ? u1[1] : u1[0];
            u1[1] = t1 ? u1[2] : u1[1];
            u1[2] = t1 ? u1[3] : u1[2];
            u1[3] = t1 ? 0u    : u1[3];
        }
        float p0[4], p1[4];
        float s0 = 0.f, s1 = 0.f;
#pragma unroll
        for (int e = 0; e < 4; e++) {
            p0[e] = (uo0[e] >= th0) ? __expf(fa0[e] - rm0) : 0.f;
            p1[e] = (uo1[e] >= th1) ? __expf(fa1[e] - rm1) : 0.f;
            s0 += p0[e]; s1 += p1[e];
        }
#pragma unroll
        for (int o = 16; o; o >>= 1) {
            s0 += __shfl_xor_sync(FULLMASK, s0, o);
            s1 += __shfl_xor_sync(FULLMASK, s1, o);
        }
        float inv0 = 1.0f / s0, inv1 = 1.0f / s1;
        // compact packed (idx, p) into 16-entry float2 lists
        int bc0 = 0, bc1 = 0;
#pragma unroll
        for (int e = 0; e < 4; e++) {
            uint32_t b0 = __ballot_sync(FULLMASK, p0[e] > 0.f);
            uint32_t b1 = __ballot_sync(FULLMASK, p1[e] > 0.f);
            uint32_t lt = (1u << lane) - 1u;
            if (p0[e] > 0.f) {
                int pos = bc0 + __popc(b0 & lt);
                if (pos < 16)
                    sP[r0 * 16 + pos] =
                        make_float2(__int_as_float(lane * 4 + e), p0[e] * inv0);
            }
            if (p1[e] > 0.f) {
                int pos = bc1 + __popc(b1 & lt);
                if (pos < 16)
                    sP[r1 * 16 + pos] =
                        make_float2(__int_as_float(lane * 4 + e), p1[e] * inv1);
            }
            bc0 += __popc(b0);
            bc1 += __popc(b1);
        }
    }
    __syncthreads();

    // ---- sparse AV over bf16 V: mixed[r] = sum_j p_j * V[idx_j] ----
    int B = bh >> 3, hh = bh & 7;
    const uint32_t* sVb = (const uint32_t*)(sm + A2_V);   // bf16x2 units
    for (int i = 0; i < 2; i++) {
        int r0 = wid * 4 + 2 * i;
        int r1 = r0 + 1;
        unsigned long long a0 = 0, a1 = 0;
#pragma unroll
        for (int j = 0; j < 16; j++) {
            float2 e0 = sP[r0 * 16 + j];
            float2 e1 = sP[r1 * 16 + j];
            int i0 = __float_as_int(e0.x);
            int i1 = __float_as_int(e1.x);
            uint32_t v0 = sVb[i0 * 32 + lane];   // bf16x2 (cols lane*2, +1)
            uint32_t v1 = sVb[i1 * 32 + lane];
            unsigned long long vv0 = pack2(__uint_as_float(v0 << 16),
                                           __uint_as_float(v0 & 0xffff0000u));
            unsigned long long vv1 = pack2(__uint_as_float(v1 << 16),
                                           __uint_as_float(v1 & 0xffff0000u));
            a0 = fma2(pack2(e0.y, e0.y), vv0, a0);
            a1 = fma2(pack2(e1.y, e1.y), vv1, a1);
        }
        size_t o0 = ((size_t)B * 128 + qr0 + r0) * 512 + hh * 64 + lane * 2;
        store_h(o0, unpack2(a0));
        store_h(o0 + 512, unpack2(a1));
    }
}

// =====================================================================
extern "C" void kernel_launch(void* const* d_in, const int* in_sizes, int n_in,
                              void* d_out, int out_size) {
    const float* h  = (const float*)d_in[0];
    const float* Wq = (const float*)d_in[1];
    const float* Wk = (const float*)d_in[2];
    const float* Wv = (const float*)d_in[3];
    const float* Wo = (const float*)d_in[4];
    float* out = (float*)d_out;

    cudaFuncSetAttribute(gemm_mma<0>, cudaFuncAttributeMaxDynamicSharedMemorySize, GEMM_SMEM);
    cudaFuncSetAttribute(gemm_mma<1>, cudaFuncAttributeMaxDynamicSharedMemorySize, GEMM_SMEM);
    cudaFuncSetAttribute(attn2, cudaFuncAttributeMaxDynamicSharedMemorySize, ATT_SMEM);

    conv_h<<<65536, 256>>>(h);
    conv_w<<<1024, 256>>>(Wq, Wk, Wv, Wo);
    gemm_mma<0><<<dim3(12, 1024), 256, GEMM_SMEM>>>(nullptr, nullptr);
    attn2<<<32768, 256, ATT_SMEM>>>();
    gemm_mma<1><<<dim3(4, 1024), 256, GEMM_SMEM>>>(h, out);
}

// round 15
// speedup vs baseline: 1.2501x; 1.0312x over previous
#include <cuda_runtime.h>
#include <cuda_bf16.h>
#include <cstdint>

// Problem dims
#define BSZ 16
#define NV  128
#define NT  64
#define DM  512
#define HEADS 8
#define HD  64
#define TOPKN 16
#define BATT (BSZ*NT)          // 1024
#define FULLMASK 0xffffffffu

#define HN ((size_t)BSZ*NV*NT*DM)   // 67,108,864 elements
#define QKN ((size_t)BATT*HEADS*NV*HD)

// ---------- scratch (device globals; no allocation allowed) ----------
__device__ __nv_bfloat16 g_Qhi[QKN];    // [B][H][V][hd], pre-scaled by 1/8
__device__ __nv_bfloat16 g_Qlo[QKN];
__device__ __nv_bfloat16 g_Khi[QKN];
__device__ __nv_bfloat16 g_Klo[QKN];
__device__ __nv_bfloat16 g_Vb[QKN];     // [B][H][V][hd] bf16
__device__ __nv_bfloat16 g_Hhi[HN];     // h split hi  [m][k], m=(b*128+v)*64+t
__device__ __nv_bfloat16 g_Hlo[HN];
__device__ __nv_bfloat16 g_Mhi[HN];     // mixed bf16 [m][k], m=(b*64+t)*128+v
__device__ __nv_bfloat16 g_Whi[4*DM*DM];  // Wq,Wk,Wv,Wo split hi [n][k]
__device__ __nv_bfloat16 g_Wlo[4*DM*DM];

// ---------- packed f32x2 helpers ----------
__device__ __forceinline__ unsigned long long pack2(float lo, float hi) {
    unsigned long long r;
    asm("mov.b64 %0, {%1, %2};" : "=l"(r) : "f"(lo), "f"(hi));
    return r;
}
__device__ __forceinline__ float2 unpack2(unsigned long long v) {
    float2 r;
    asm("mov.b64 {%0, %1}, %2;" : "=f"(r.x), "=f"(r.y) : "l"(v));
    return r;
}
__device__ __forceinline__ unsigned long long fma2(unsigned long long a,
                                                   unsigned long long b,
                                                   unsigned long long c) {
    unsigned long long d;
    asm("fma.rn.f32x2 %0, %1, %2, %3;" : "=l"(d) : "l"(a), "l"(b), "l"(c));
    return d;
}

// ---------- misc helpers ----------
__device__ __forceinline__ uint32_t smem_u32(const void* p) {
    uint32_t a;
    asm("{ .reg .u64 t; cvta.to.shared.u64 t, %1; cvt.u32.u64 %0, t; }"
        : "=r"(a) : "l"(p));
    return a;
}
__device__ __forceinline__ void split1(float x, __nv_bfloat16& h, __nv_bfloat16& l) {
    h = __float2bfloat16(x);
    l = __float2bfloat16(x - __bfloat162float(h));
}
__device__ __forceinline__ uint32_t redux_max_u32(uint32_t v) {
    uint32_t r;
    asm volatile("redux.sync.max.u32 %0, %1, 0xffffffff;" : "=r"(r) : "r"(v));
    return r;
}
// monotonic float->uint map (order-preserving)
__device__ __forceinline__ uint32_t f2u(float x) {
    uint32_t u = __float_as_uint(x);
    return u ^ (uint32_t)(((int32_t)u >> 31) | 0x80000000);
}
__device__ __forceinline__ float u2f(uint32_t u) {
    uint32_t x = (u >> 31) ? (u ^ 0x80000000u) : ~u;
    return __uint_as_float(x);
}
__device__ __forceinline__ void csw(uint32_t& a, uint32_t& b) {  // desc compare-swap
    uint32_t hi = max(a, b), lo = min(a, b);
    a = hi; b = lo;
}

// ---------- fused bf16 split pre-conversion (h + all 4 weights) ----------
__global__ void __launch_bounds__(256) conv_all(const float* __restrict__ h,
                                                const float* __restrict__ q,
                                                const float* __restrict__ k,
                                                const float* __restrict__ v,
                                                const float* __restrict__ o) {
    int bid = blockIdx.x;
    if (bid < 65536) {
        size_t i = ((size_t)bid * 256 + threadIdx.x) * 4;
        float4 f = *(const float4*)(h + i);
        __nv_bfloat16 h0,l0,h1,l1,h2,l2,h3,l3;
        split1(f.x,h0,l0); split1(f.y,h1,l1); split1(f.z,h2,l2); split1(f.w,h3,l3);
        ushort4 H = { __bfloat16_as_ushort(h0), __bfloat16_as_ushort(h1),
                      __bfloat16_as_ushort(h2), __bfloat16_as_ushort(h3) };
        ushort4 L = { __bfloat16_as_ushort(l0), __bfloat16_as_ushort(l1),
                      __bfloat16_as_ushort(l2), __bfloat16_as_ushort(l3) };
        *(ushort4*)(g_Hhi + i) = H;
        *(ushort4*)(g_Hlo + i) = L;
    } else {
        size_t i4 = (size_t)(bid - 65536) * 256 + threadIdx.x;
        int w = (int)(i4 >> 16);
        const float* s = (w == 0) ? q : (w == 1) ? k : (w == 2) ? v : o;
        size_t loc = (i4 & 65535) * 4;
        size_t i = i4 * 4;
        float4 f = *(const float4*)(s + loc);
        __nv_bfloat16 h0,l0,h1,l1,h2,l2,h3,l3;
        split1(f.x,h0,l0); split1(f.y,h1,l1); split1(f.z,h2,l2); split1(f.w,h3,l3);
        ushort4 H = { __bfloat16_as_ushort(h0), __bfloat16_as_ushort(h1),
                      __bfloat16_as_ushort(h2), __bfloat16_as_ushort(h3) };
        ushort4 L = { __bfloat16_as_ushort(l0), __bfloat16_as_ushort(l1),
                      __bfloat16_as_ushort(l2), __bfloat16_as_ushort(l3) };
        *(ushort4*)(g_Whi + i) = H;
        *(ushort4*)(g_Wlo + i) = L;
    }
}

// ---------- shared GEMM plumbing ----------
#define STAGE_B   32768
#define GEMM_SMEM (3*STAGE_B)   // 3-stage ring, 96KB

__device__ __forceinline__ uint32_t swz(uint32_t off) {     // 64B rows
    return off ^ (((off >> 6) & 7) << 4);
}
__device__ __forceinline__ uint32_t swz128(uint32_t off) {  // 128B rows
    return off ^ (((off >> 7) & 7) << 4);
}

#define CPA16(dst, src) \
    asm volatile("cp.async.cg.shared.global [%0], [%1], 16;" :: "r"(dst), "l"(src))
#define CPCOMMIT() asm volatile("cp.async.commit_group;" ::: "memory")
#define CPWAIT(n)  asm volatile("cp.async.wait_group %0;" :: "n"(n) : "memory")

#define LDSM4(r, a) \
    asm volatile("ldmatrix.sync.aligned.m8n8.x4.shared.b16 {%0,%1,%2,%3}, [%4];" \
        : "=r"((r)[0]),"=r"((r)[1]),"=r"((r)[2]),"=r"((r)[3]) : "r"(a))

#define MMA16816(d, a, b0, b1) \
    asm volatile("mma.sync.aligned.m16n8k16.row.col.f32.bf16.bf16.f32 " \
        "{%0,%1,%2,%3},{%4,%5,%6,%7},{%8,%9},{%0,%1,%2,%3};" \
        : "+f"((d)[0]),"+f"((d)[1]),"+f"((d)[2]),"+f"((d)[3]) \
        : "r"((a)[0]),"r"((a)[1]),"r"((a)[2]),"r"((a)[3]), "r"(b0),"r"(b1))

// ---------- Q/K projection GEMM (3-product split, k=32 chunks) ----------
__global__ void __launch_bounds__(256, 2) gemm_qk()
{
    extern __shared__ char sm[];
    uint32_t sb = smem_u32(sm);
    int tid = threadIdx.x, lane = tid & 31, wid = tid >> 5;
    int bx = blockIdx.x;                 // 0..7: wsel(0..1) x 4 n-tiles
    int m0 = blockIdx.y * 128;
    int wsel = bx >> 2;
    int n0 = (bx & 3) * 128;

    const __nv_bfloat16* Ahi = g_Hhi;
    const __nv_bfloat16* Alo = g_Hlo;
    const __nv_bfloat16* Bhi = g_Whi + (size_t)wsel * DM * DM;
    const __nv_bfloat16* Blo = g_Wlo + (size_t)wsel * DM * DM;

    auto loadc = [&](int c) {
        uint32_t stb = sb + (uint32_t)(c % 3) * STAGE_B;
#pragma unroll
        for (int i = 0; i < 8; i++) {
            int g = tid + i * 256;
            int tile = g >> 9;
            int idx = g & 511;
            int row = idx >> 2, kg = idx & 3;
            const __nv_bfloat16* src;
            if (tile == 0)      src = Ahi + (size_t)(m0 + row) * 512;
            else if (tile == 1) src = Alo + (size_t)(m0 + row) * 512;
            else if (tile == 2) src = Bhi + (size_t)(n0 + row) * 512;
            else                src = Blo + (size_t)(n0 + row) * 512;
            src += c * 32 + kg * 8;
            uint32_t dst = stb + tile * 8192 + swz((uint32_t)(row * 64 + kg * 16));
            CPA16(dst, src);
        }
        CPCOMMIT();
    };

    int wm = wid & 3, wn = wid >> 2;      // warp tile: 32(M) x 64(N)
    float acc[64];
#pragma unroll
    for (int i = 0; i < 64; i++) acc[i] = 0.f;

    loadc(0);
    loadc(1);
    for (int c = 0; c < 16; c++) {
        if (c == 15) { CPWAIT(0); } else { CPWAIT(1); }
        __syncthreads();
        if (c + 2 < 16) loadc(c + 2);
        uint32_t stb = sb + (uint32_t)(c % 3) * STAGE_B;
#pragma unroll
        for (int ks = 0; ks < 2; ks++) {
            uint32_t ah[2][4], al[2][4];
#pragma unroll
            for (int mt = 0; mt < 2; mt++) {
                int r = wm * 32 + mt * 16 + (lane & 15);
                uint32_t off = swz((uint32_t)(r * 64 + (ks * 16 + (lane >> 4) * 8) * 2));
                LDSM4(ah[mt], stb + off);
                LDSM4(al[mt], stb + 8192 + off);
            }
#pragma unroll
            for (int p = 0; p < 4; p++) {
                int rr = wn * 64 + (2 * p + (lane >> 4)) * 8 + (lane & 7);
                uint32_t off = swz((uint32_t)(rr * 64 + (ks * 16 + ((lane >> 3) & 1) * 8) * 2));
                uint32_t bh[4], bl[4];
                LDSM4(bh, stb + 16384 + off);
                LDSM4(bl, stb + 24576 + off);
#pragma unroll
                for (int pr = 0; pr < 3; pr++) {
#pragma unroll
                    for (int mt = 0; mt < 2; mt++) {
#pragma unroll
                        for (int q = 0; q < 2; q++) {
                            float* d = acc + mt * 32 + (2 * p + q) * 4;
                            const uint32_t* a = (pr == 2) ? al[mt] : ah[mt];
                            const uint32_t* b = (pr == 1) ? bl : bh;
                            MMA16816(d, a, b[2 * q], b[2 * q + 1]);
                        }
                    }
                }
            }
        }
    }

    // ---- epilogue: Q (scaled) / K bf16 hi-lo splits ----
#pragma unroll
    for (int mt = 0; mt < 2; mt++) {
#pragma unroll
        for (int half = 0; half < 2; half++) {
            int m = m0 + wm * 32 + mt * 16 + half * 8 + (lane >> 2);
            int b = m >> 13, v = (m >> 6) & 127, t = m & 63;
            int head = (n0 >> 6) + wn;
            size_t rb = (((size_t)(b * 64 + t) * 8 + head) * 128 + v) * 64
                        + (lane & 3) * 2;
#pragma unroll
            for (int nt = 0; nt < 8; nt++) {
                int base = mt * 32 + nt * 4 + half * 2;
                float2 val = make_float2(acc[base], acc[base + 1]);
                size_t g = rb + nt * 8;
                if (wsel == 0) { val.x *= 0.125f; val.y *= 0.125f; }
                __nv_bfloat16 h0, l0, h1, l1;
                split1(val.x, h0, l0);
                split1(val.y, h1, l1);
                ushort2 H = { __bfloat16_as_ushort(h0), __bfloat16_as_ushort(h1) };
                ushort2 L = { __bfloat16_as_ushort(l0), __bfloat16_as_ushort(l1) };
                if (wsel == 0) {
                    *(ushort2*)(g_Qhi + g) = H;
                    *(ushort2*)(g_Qlo + g) = L;
                } else {
                    *(ushort2*)(g_Khi + g) = H;
                    *(ushort2*)(g_Klo + g) = L;
                }
            }
        }
    }
}

// ---------- 1-product GEMM, k=64 chunks (V projection / out-proj) ----------
// MODE 0: V proj (A=g_Hhi, B=Wv_hi, out=g_Vb bf16 scatter)
// MODE 1: out-proj (A=g_Mhi, B=Wo_hi, out = h + A@Wo^T)
template <int MODE>
__global__ void __launch_bounds__(256, 2) gemm_1p(
    const float* __restrict__ hres, float* __restrict__ outp)
{
    extern __shared__ char sm[];
    uint32_t sb = smem_u32(sm);
    int tid = threadIdx.x, lane = tid & 31, wid = tid >> 5;
    int n0 = blockIdx.x * 128;
    int m0 = blockIdx.y * 128;

    const __nv_bfloat16* Ahi = (MODE == 0) ? g_Hhi : g_Mhi;
    const __nv_bfloat16* Bhi = g_Whi + (size_t)((MODE == 0) ? 2 : 3) * DM * DM;

    // stage: A [128 rows x 128B] 16KB | B 16KB  (128B rows, swz128)
    auto loadc = [&](int c) {
        uint32_t stb = sb + (uint32_t)(c % 3) * STAGE_B;
#pragma unroll
        for (int i = 0; i < 8; i++) {
            int g = tid + i * 256;            // 0..2047
            int tile = g >> 10;               // 0:A 1:B
            int idx = g & 1023;
            int row = idx >> 3, kg = idx & 7;
            const __nv_bfloat16* src = (tile == 0)
                ? Ahi + (size_t)(m0 + row) * 512
                : Bhi + (size_t)(n0 + row) * 512;
            src += c * 64 + kg * 8;
            uint32_t dst = stb + tile * 16384 + swz128((uint32_t)(row * 128 + kg * 16));
            CPA16(dst, src);
        }
        CPCOMMIT();
    };

    int wm = wid & 3, wn = wid >> 2;      // warp tile: 32(M) x 64(N)
    float acc[64];
#pragma unroll
    for (int i = 0; i < 64; i++) acc[i] = 0.f;

    loadc(0);
    loadc(1);
    for (int c = 0; c < 8; c++) {
        if (c == 7) { CPWAIT(0); } else { CPWAIT(1); }
        __syncthreads();
        if (c + 2 < 8) loadc(c + 2);
        uint32_t stb = sb + (uint32_t)(c % 3) * STAGE_B;
#pragma unroll
        for (int ks = 0; ks < 4; ks++) {
            uint32_t ah[2][4];
#pragma unroll
            for (int mt = 0; mt < 2; mt++) {
                int r = wm * 32 + mt * 16 + (lane & 15);
                uint32_t off = swz128((uint32_t)(r * 128 + (ks * 16 + (lane >> 4) * 8) * 2));
                LDSM4(ah[mt], stb + off);
            }
#pragma unroll
            for (int p = 0; p < 4; p++) {
                int rr = wn * 64 + (2 * p + (lane >> 4)) * 8 + (lane & 7);
                uint32_t off = swz128((uint32_t)(rr * 128 + (ks * 16 + ((lane >> 3) & 1) * 8) * 2));
                uint32_t bh[4];
                LDSM4(bh, stb + 16384 + off);
#pragma unroll
                for (int mt = 0; mt < 2; mt++) {
#pragma unroll
                    for (int q = 0; q < 2; q++) {
                        float* d = acc + mt * 32 + (2 * p + q) * 4;
                        MMA16816(d, ah[mt], bh[2 * q], bh[2 * q + 1]);
                    }
                }
            }
        }
    }

    // ---- epilogue ----
#pragma unroll
    for (int mt = 0; mt < 2; mt++) {
#pragma unroll
        for (int half = 0; half < 2; half++) {
            int m = m0 + wm * 32 + mt * 16 + half * 8 + (lane >> 2);
            if (MODE == 0) {
                int b = m >> 13, v = (m >> 6) & 127, t = m & 63;
                int head = (n0 >> 6) + wn;
                size_t rb = (((size_t)(b * 64 + t) * 8 + head) * 128 + v) * 64
                            + (lane & 3) * 2;
#pragma unroll
                for (int nt = 0; nt < 8; nt++) {
                    int base = mt * 32 + nt * 4 + half * 2;
                    float2 val = make_float2(acc[base], acc[base + 1]);
                    ushort2 V2 = { __bfloat16_as_ushort(__float2bfloat16(val.x)),
                                   __bfloat16_as_ushort(__float2bfloat16(val.y)) };
                    *(ushort2*)(g_Vb + rb + nt * 8) = V2;
                }
            } else {
                int Bi = m >> 7, v = m & 127;
                int b = Bi >> 6, t = Bi & 63;
                size_t dbase = (((size_t)b * 128 + v) * 64 + t) * 512
                               + n0 + wn * 64 + (lane & 3) * 2;
#pragma unroll
                for (int nt = 0; nt < 8; nt++) {
                    int base = mt * 32 + nt * 4 + half * 2;
                    float2 val = make_float2(acc[base], acc[base + 1]);
                    size_t d = dbase + nt * 8;
                    float2 hv = *(const float2*)&hres[d];
                    val.x += hv.x; val.y += hv.y;
                    *(float2*)&outp[d] = val;
                }
            }
        }
    }
}

// =====================================================================
// Attention v8 (round-14 proven): 32 q-rows per CTA, 56KB smem, 4 CTA/SM.
// =====================================================================
#define A2_QHI 0                // [32][128B]  4KB
#define A2_QLO 4096             // 4KB
#define A2_KHI 8192             // [128][128B] 16KB
#define A2_KLO 24576            // 16KB (K ends 40960)
#define A2_V   40960            // bf16 [128][64] = 16KB (ends 57344)
#define A2_S   0                // overlays Q + KHI[0:8K]: fp32 [32][128] = 16KB
#define A2_P   16384            // overlays KHI[8K:12K]: float2 [32][16] = 4KB
#define ATT_SMEM 57344

// XOR bank-swizzled S index ([32][128] fp32)
__device__ __forceinline__ int sidx(int r, int c) {
    return r * 128 + (c ^ ((r & 7) << 2));
}

__device__ __forceinline__ void store_h(size_t idx, float2 v) {
    ushort2 H = { __bfloat16_as_ushort(__float2bfloat16(v.x)),
                  __bfloat16_as_ushort(__float2bfloat16(v.y)) };
    *(ushort2*)(g_Mhi + idx) = H;
}

__global__ void __launch_bounds__(256, 4) attn2() {
    extern __shared__ char sm[];
    uint32_t sb = smem_u32(sm);
    float* sS = (float*)(sm + A2_S);
    float2* sP = (float2*)(sm + A2_P);

    int tid = threadIdx.x, lane = tid & 31, wid = tid >> 5;
    int bx = blockIdx.x;                 // ((B*8+head)<<2) | quarter
    int bh = bx >> 2;
    int qr0 = (bx & 3) * 32;             // q-row offset within the 128
    size_t base = (size_t)bh * 8192;     // 128*64

    // ---- async loads: Q quarter (32 rows), K full, V bf16 ----
    {
        int g = tid;                     // 0..255 (32 rows x 8 chunks)
        int row = g >> 3, kg = g & 7;
        uint32_t doff = swz128((uint32_t)(row * 128 + kg * 16));
        CPA16(sb + A2_QHI + doff, g_Qhi + base + (size_t)(qr0 + row) * 64 + kg * 8);
        CPA16(sb + A2_QLO + doff, g_Qlo + base + (size_t)(qr0 + row) * 64 + kg * 8);
    }
#pragma unroll
    for (int i = 0; i < 4; i++) {
        int g = tid + i * 256;           // 0..1023 (128 rows x 8 chunks)
        int row = g >> 3, kg = g & 7;
        uint32_t doff = swz128((uint32_t)(row * 128 + kg * 16));
        CPA16(sb + A2_KHI + doff, g_Khi + base + (size_t)row * 64 + kg * 8);
        CPA16(sb + A2_KLO + doff, g_Klo + base + (size_t)row * 64 + kg * 8);
    }
#pragma unroll
    for (int i = 0; i < 4; i++) {
        int g = tid + i * 256;           // 0..1023 chunks of 16B (16KB)
        CPA16(sb + A2_V + g * 16, g_Vb + base + g * 8);
    }
    CPCOMMIT();
    CPWAIT(0);
    __syncthreads();

    // ---- S = Q @ K^T via mma (3-product split). warp tile 32(M) x 16(N) ----
    {
        float acc[16];
#pragma unroll
        for (int i = 0; i < 16; i++) acc[i] = 0.f;
#pragma unroll
        for (int kt = 0; kt < 4; kt++) {
            uint32_t ah[2][4], al[2][4];
#pragma unroll
            for (int mt = 0; mt < 2; mt++) {
                int r = mt * 16 + (lane & 15);
                uint32_t off = swz128((uint32_t)(r * 128 + (kt * 16 + (lane >> 4) * 8) * 2));
                LDSM4(ah[mt], sb + A2_QHI + off);
                LDSM4(al[mt], sb + A2_QLO + off);
            }
            {
                int rr = wid * 16 + (lane >> 4) * 8 + (lane & 7);
                uint32_t off = swz128((uint32_t)(rr * 128 + (kt * 16 + ((lane >> 3) & 1) * 8) * 2));
                uint32_t bh4[4], bl4[4];
                LDSM4(bh4, sb + A2_KHI + off);
                LDSM4(bl4, sb + A2_KLO + off);
#pragma unroll
                for (int pr = 0; pr < 3; pr++) {
#pragma unroll
                    for (int mt = 0; mt < 2; mt++) {
#pragma unroll
                        for (int q = 0; q < 2; q++) {
                            float* d = acc + mt * 8 + q * 4;
                            const uint32_t* a = (pr == 2) ? al[mt] : ah[mt];
                            const uint32_t* b = (pr == 1) ? bl4 : bh4;
                            MMA16816(d, a, b[2 * q], b[2 * q + 1]);
                        }
                    }
                }
            }
        }
        __syncthreads();   // all warps done reading Q/K before S/P overwrite them
        // store S to overlaid SMEM [32][128] with XOR swizzle
#pragma unroll
        for (int mt = 0; mt < 2; mt++) {
#pragma unroll
            for (int half = 0; half < 2; half++) {
                int r = mt * 16 + half * 8 + (lane >> 2);
#pragma unroll
                for (int nt = 0; nt < 2; nt++) {
                    int col = wid * 16 + nt * 8 + (lane & 3) * 2;
                    int bi = mt * 8 + nt * 4 + half * 2;
                    *(float2*)&sS[sidx(r, col)] = make_float2(acc[bi], acc[bi + 1]);
                }
            }
        }
        // zero compacted-P lists (overlays dead KHI region; safe after sync)
        for (int i = tid; i < 512; i += 256) sP[i] = make_float2(0.f, 0.f);
    }
    __syncthreads();

    // ---- top-16 (sorted tournament) + softmax, warp per 2 rows x 2 iters ----
    for (int i = 0; i < 2; i++) {
        int r0 = wid * 4 + 2 * i;
        int r1 = r0 + 1;
        float4 f0 = *(float4*)&sS[sidx(r0, lane * 4)];
        float4 f1 = *(float4*)&sS[sidx(r1, lane * 4)];
        float fa0[4] = { f0.x, f0.y, f0.z, f0.w };
        float fa1[4] = { f1.x, f1.y, f1.z, f1.w };
        uint32_t uo0[4], uo1[4], u0[4], u1[4];
#pragma unroll
        for (int e = 0; e < 4; e++) {
            uo0[e] = u0[e] = f2u(fa0[e]);
            uo1[e] = u1[e] = f2u(fa1[e]);
        }
        // per-lane descending sort of 4 values (sorting network)
        csw(u0[0], u0[2]); csw(u0[1], u0[3]);
        csw(u0[0], u0[1]); csw(u0[2], u0[3]); csw(u0[1], u0[2]);
        csw(u1[0], u1[2]); csw(u1[1], u1[3]);
        csw(u1[0], u1[1]); csw(u1[2], u1[3]); csw(u1[1], u1[2]);

        float rm0 = 0.f, rm1 = 0.f;
        uint32_t th0 = 0, th1 = 0;
#pragma unroll 1
        for (int it = 0; it < TOPKN; it++) {
            uint32_t g0 = redux_max_u32(u0[0]);
            uint32_t g1 = redux_max_u32(u1[0]);
            if (it == 0) { rm0 = u2f(g0); rm1 = u2f(g1); }
            th0 = g0; th1 = g1;
            bool t0 = (u0[0] == g0);
            bool t1 = (u1[0] == g1);
            u0[0] = t0 ? u0[1] : u0[0];
            u0[1] = t0 ? u0[2] : u0[1];
            u0[2] = t0 ? u0[3] : u0[2];
            u0[3] = t0 ? 0u    : u0[3];
            u1[0] = t1 ? u1[1] : u1[0];
            u1[1] = t1 ? u1[2] : u1[1];
            u1[2] = t1 ? u1[3] : u1[2];
            u1[3] = t1 ? 0u    : u1[3];
        }
        float p0[4], p1[4];
        float s0 = 0.f, s1 = 0.f;
#pragma unroll
        for (int e = 0; e < 4; e++) {
            p0[e] = (uo0[e] >= th0) ? __expf(fa0[e] - rm0) : 0.f;
            p1[e] = (uo1[e] >= th1) ? __expf(fa1[e] - rm1) : 0.f;
            s0 += p0[e]; s1 += p1[e];
        }
#pragma unroll
        for (int o = 16; o; o >>= 1) {
            s0 += __shfl_xor_sync(FULLMASK, s0, o);
            s1 += __shfl_xor_sync(FULLMASK, s1, o);
        }
        float inv0 = 1.0f / s0, inv1 = 1.0f / s1;
        // compact packed (idx, p) into 16-entry float2 lists
        int bc0 = 0, bc1 = 0;
#pragma unroll
        for (int e = 0; e < 4; e++) {
            uint32_t b0 = __ballot_sync(FULLMASK, p0[e] > 0.f);
            uint32_t b1 = __ballot_sync(FULLMASK, p1[e] > 0.f);
            uint32_t lt = (1u << lane) - 1u;
            if (p0[e] > 0.f) {
                int pos = bc0 + __popc(b0 & lt);
                if (pos < 16)
                    sP[r0 * 16 + pos] =
                        make_float2(__int_as_float(lane * 4 + e), p0[e] * inv0);
            }
            if (p1[e] > 0.f) {
                int pos = bc1 + __popc(b1 & lt);
                if (pos < 16)
                    sP[r1 * 16 + pos] =
                        make_float2(__int_as_float(lane * 4 + e), p1[e] * inv1);
            }
            bc0 += __popc(b0);
            bc1 += __popc(b1);
        }
    }
    __syncthreads();

    // ---- sparse AV over bf16 V: mixed[r] = sum_j p_j * V[idx_j] ----
    int B = bh >> 3, hh = bh & 7;
    const uint32_t* sVb = (const uint32_t*)(sm + A2_V);   // bf16x2 units
    for (int i = 0; i < 2; i++) {
        int r0 = wid * 4 + 2 * i;
        int r1 = r0 + 1;
        unsigned long long a0 = 0, a1 = 0;
#pragma unroll
        for (int j = 0; j < 16; j++) {
            float2 e0 = sP[r0 * 16 + j];
            float2 e1 = sP[r1 * 16 + j];
            int i0 = __float_as_int(e0.x);
            int i1 = __float_as_int(e1.x);
            uint32_t v0 = sVb[i0 * 32 + lane];   // bf16x2 (cols lane*2, +1)
            uint32_t v1 = sVb[i1 * 32 + lane];
            unsigned long long vv0 = pack2(__uint_as_float(v0 << 16),
                                           __uint_as_float(v0 & 0xffff0000u));
            unsigned long long vv1 = pack2(__uint_as_float(v1 << 16),
                                           __uint_as_float(v1 & 0xffff0000u));
            a0 = fma2(pack2(e0.y, e0.y), vv0, a0);
            a1 = fma2(pack2(e1.y, e1.y), vv1, a1);
        }
        size_t o0 = ((size_t)B * 128 + qr0 + r0) * 512 + hh * 64 + lane * 2;
        store_h(o0, unpack2(a0));
        store_h(o0 + 512, unpack2(a1));
    }
}

// =====================================================================
extern "C" void kernel_launch(void* const* d_in, const int* in_sizes, int n_in,
                              void* d_out, int out_size) {
    const float* h  = (const float*)d_in[0];
    const float* Wq = (const float*)d_in[1];
    const float* Wk = (const float*)d_in[2];
    const float* Wv = (const float*)d_in[3];
    const float* Wo = (const float*)d_in[4];
    float* out = (float*)d_out;

    cudaFuncSetAttribute(gemm_qk,   cudaFuncAttributeMaxDynamicSharedMemorySize, GEMM_SMEM);
    cudaFuncSetAttribute(gemm_1p<0>, cudaFuncAttributeMaxDynamicSharedMemorySize, GEMM_SMEM);
    cudaFuncSetAttribute(gemm_1p<1>, cudaFuncAttributeMaxDynamicSharedMemorySize, GEMM_SMEM);
    cudaFuncSetAttribute(attn2,     cudaFuncAttributeMaxDynamicSharedMemorySize, ATT_SMEM);

    conv_all<<<66560, 256>>>(h, Wq, Wk, Wv, Wo);
    gemm_qk<<<dim3(8, 1024), 256, GEMM_SMEM>>>();
    gemm_1p<0><<<dim3(4, 1024), 256, GEMM_SMEM>>>(nullptr, nullptr);
    attn2<<<32768, 256, ATT_SMEM>>>();
    gemm_1p<1><<<dim3(4, 1024), 256, GEMM_SMEM>>>(h, out);
}